// round 1
// baseline (speedup 1.0000x reference)
#include <cuda_runtime.h>
#include <math.h>

// ---------------------------------------------------------------------------
// SwinTLayer: B=4, H=64, W=128, C=512, F=1024, NH=8, hd=64, WS=4, SS=2
// Window tokens N=16, windows per image 16*32=512, total windows 2048,
// total window-rows ROWS = 32768.
// ---------------------------------------------------------------------------

#define BATCH   4
#define IMH     64
#define IMW     128
#define CDIM    512
#define LTOK    (IMH*IMW)            // 8192
#define NHEADS  8
#define HDIM    64
#define NWTOK   16                    // tokens per window
#define NWINDOWS 2048                 // BATCH * 16 * 32
#define ROWS    (NWINDOWS*NWTOK)      // 32768
#define FDIM    1024

// Scratch (static device allocations — allowed; cudaMalloc is not)
__device__ float g_xw [ (size_t)ROWS*CDIM ];      // LN1 + shift + window partition
__device__ float g_qkv[ (size_t)ROWS*3*CDIM ];    // qkv projection
__device__ float g_ow [ (size_t)ROWS*CDIM ];      // attention output (window layout)
__device__ float g_x2 [ (size_t)BATCH*LTOK*CDIM ];// shortcut + attn (token layout)
__device__ float g_h2 [ (size_t)BATCH*LTOK*CDIM ];// LN2 output
__device__ float g_m1 [ (size_t)ROWS*FDIM ];      // gelu(h2 @ w1^T + b1)

// Map a window-layout row r (window*16 + n) to its token-layout row.
// Window (b, wi, wj), intra-window (dy, dx) -> shifted pixel (hs, ws)
// -> original pixel ((hs+2)%64, (ws+2)%128).  Same map for gather (LN1 input)
// and scatter (window-reverse + un-shift).
__device__ __forceinline__ int swin_token(int r)
{
    int win   = r >> 4;
    int n     = r & 15;
    int b     = win >> 9;           // /512
    int local = win & 511;
    int wi    = local >> 5;         // 0..15
    int wj    = local & 31;         // 0..31
    int hs    = wi * 4 + (n >> 2);
    int ws    = wj * 4 + (n & 3);
    int h     = (hs + 2) & (IMH - 1);
    int w     = (ws + 2) & (IMW - 1);
    return b * LTOK + h * IMW + w;
}

// ---------------------------------------------------------------------------
// LayerNorm over C=512.  128 threads, float4 per thread.
// GATHER=true: src row = swin_token(blockIdx.x) of x  (LN1 + shift + partition)
// GATHER=false: src row = blockIdx.x                   (LN2)
// ---------------------------------------------------------------------------
template <bool GATHER>
__global__ void ln_kernel(const float* __restrict__ src,
                          const float* __restrict__ gamma,
                          const float* __restrict__ beta,
                          float* __restrict__ dst)
{
    int r    = blockIdx.x;
    int srow = GATHER ? swin_token(r) : r;
    const float4* in = (const float4*)(src + (size_t)srow * CDIM);
    float4 v = in[threadIdx.x];

    float s  = v.x + v.y + v.z + v.w;
    float sq = v.x*v.x + v.y*v.y + v.z*v.z + v.w*v.w;
    #pragma unroll
    for (int o = 16; o; o >>= 1) {
        s  += __shfl_xor_sync(0xffffffffu, s,  o);
        sq += __shfl_xor_sync(0xffffffffu, sq, o);
    }
    __shared__ float ss[4], ssq[4];
    int warp = threadIdx.x >> 5;
    if ((threadIdx.x & 31) == 0) { ss[warp] = s; ssq[warp] = sq; }
    __syncthreads();
    s  = ss[0] + ss[1] + ss[2] + ss[3];
    sq = ssq[0] + ssq[1] + ssq[2] + ssq[3];

    float mean = s * (1.0f / CDIM);
    float var  = sq * (1.0f / CDIM) - mean * mean;
    float rstd = rsqrtf(var + 1e-5f);

    float4 gv = ((const float4*)gamma)[threadIdx.x];
    float4 bv = ((const float4*)beta)[threadIdx.x];
    float4 o;
    o.x = (v.x - mean) * rstd * gv.x + bv.x;
    o.y = (v.y - mean) * rstd * gv.y + bv.y;
    o.z = (v.z - mean) * rstd * gv.z + bv.z;
    o.w = (v.w - mean) * rstd * gv.w + bv.w;
    ((float4*)(dst + (size_t)r * CDIM))[threadIdx.x] = o;
}

// ---------------------------------------------------------------------------
// SGEMM: C[M,N] = A[M,K] @ B[N,K]^T + bias[N]   (both operands K-contiguous)
// 128x128 tile, BK=8, 256 threads, 8x8 per-thread register tile.
// All shapes used here divide the tiles exactly -> no bounds checks.
// Epilogues:
//   0: bias
//   1: bias + exact GELU
//   2: bias + aux[row,col] added, write C         (FC2: +x2 -> d_out)
//   3: bias + swin-permuted residual: t = swin_token(row);
//      C[t,col] = val + aux[t,col]                (proj: +shortcut -> g_x2)
// ---------------------------------------------------------------------------
template <int EPI>
__global__ void __launch_bounds__(256, 2)
sgemm_kernel(const float* __restrict__ A, const float* __restrict__ B,
             const float* __restrict__ bias, const float* __restrict__ aux,
             float* __restrict__ C, int M, int Nn, int K)
{
    __shared__ float As[8][128];
    __shared__ float Bs[8][128];

    int t    = threadIdx.x;
    int row0 = blockIdx.y * 128;
    int col0 = blockIdx.x * 128;

    int lr = t >> 1;          // 0..127
    int lp = (t & 1) * 4;     // 0 or 4

    const float* Ap = A + (size_t)(row0 + lr) * K + lp;
    const float* Bp = B + (size_t)(col0 + lr) * K + lp;

    int ty = t >> 4, tx = t & 15;
    int ry = ty * 8, rx = tx * 8;

    float acc[8][8];
    #pragma unroll
    for (int i = 0; i < 8; i++)
        #pragma unroll
        for (int j = 0; j < 8; j++) acc[i][j] = 0.0f;

    for (int kk = 0; kk < K; kk += 8) {
        float4 av = *(const float4*)(Ap + kk);
        float4 bv = *(const float4*)(Bp + kk);
        As[lp + 0][lr] = av.x; As[lp + 1][lr] = av.y;
        As[lp + 2][lr] = av.z; As[lp + 3][lr] = av.w;
        Bs[lp + 0][lr] = bv.x; Bs[lp + 1][lr] = bv.y;
        Bs[lp + 2][lr] = bv.z; Bs[lp + 3][lr] = bv.w;
        __syncthreads();

        #pragma unroll
        for (int k = 0; k < 8; k++) {
            float a[8], b[8];
            #pragma unroll
            for (int i = 0; i < 8; i++) a[i] = As[k][ry + i];
            #pragma unroll
            for (int j = 0; j < 8; j++) b[j] = Bs[k][rx + j];
            #pragma unroll
            for (int i = 0; i < 8; i++)
                #pragma unroll
                for (int j = 0; j < 8; j++) acc[i][j] += a[i] * b[j];
        }
        __syncthreads();
    }

    #pragma unroll
    for (int i = 0; i < 8; i++) {
        int gr = row0 + ry + i;
        int tt = (EPI == 3) ? swin_token(gr) : gr;
        #pragma unroll
        for (int j = 0; j < 8; j++) {
            int gc = col0 + rx + j;
            float val = acc[i][j] + bias[gc];
            if (EPI == 1) {
                val = 0.5f * val * (1.0f + erff(val * 0.70710678118654752f));
            } else if (EPI == 2) {
                val += aux[(size_t)gr * Nn + gc];
            } else if (EPI == 3) {
                val += aux[(size_t)tt * CDIM + gc];
            }
            if (EPI == 3) C[(size_t)tt * CDIM + gc] = val;
            else          C[(size_t)gr * Nn + gc]   = val;
        }
    }
}

// ---------------------------------------------------------------------------
// Windowed attention: one block per (window, head).  N=16 tokens, hd=64.
// Relative-position bias and shifted-window mask computed analytically.
// ---------------------------------------------------------------------------
__global__ void attn_kernel(const float* __restrict__ rpb)
{
    __shared__ float q[16][64], k[16][64], v[16][64];
    __shared__ float s[16][16];
    __shared__ int   cnt[16];

    int blk  = blockIdx.x;
    int win  = blk >> 3;
    int head = blk & 7;
    int t    = threadIdx.x;

    int local = win & 511;
    int wi = local >> 5, wj = local & 31;
    if (t < 16) {
        int hs = wi * 4 + (t >> 2);
        int ws = wj * 4 + (t & 3);
        int rh = hs < (IMH - 4) ? 0 : (hs < (IMH - 2) ? 1 : 2);
        int rw = ws < (IMW - 4) ? 0 : (ws < (IMW - 2) ? 1 : 2);
        cnt[t] = rh * 3 + rw;
    }

    // Load Q (scaled), K, V for this head: 16x64 each, 2 float4 per thread
    size_t base = (size_t)(win * 16) * (3 * CDIM) + head * HDIM;
    #pragma unroll
    for (int rep = 0; rep < 2; rep++) {
        int slot = t + rep * 128;          // 0..255
        int n  = slot >> 4;
        int d4 = (slot & 15) * 4;
        size_t roff = base + (size_t)n * (3 * CDIM) + d4;
        float4 qv = *(const float4*)(g_qkv + roff);
        float4 kv = *(const float4*)(g_qkv + roff + CDIM);
        float4 vv = *(const float4*)(g_qkv + roff + 2 * CDIM);
        q[n][d4+0] = qv.x * 0.125f; q[n][d4+1] = qv.y * 0.125f;
        q[n][d4+2] = qv.z * 0.125f; q[n][d4+3] = qv.w * 0.125f;
        k[n][d4+0] = kv.x; k[n][d4+1] = kv.y; k[n][d4+2] = kv.z; k[n][d4+3] = kv.w;
        v[n][d4+0] = vv.x; v[n][d4+1] = vv.y; v[n][d4+2] = vv.z; v[n][d4+3] = vv.w;
    }
    __syncthreads();

    // Logits + bias + mask (2 entries per thread)
    #pragma unroll
    for (int rep = 0; rep < 2; rep++) {
        int e = t + rep * 128;
        int i = e >> 4, j = e & 15;
        float acc = 0.0f;
        #pragma unroll
        for (int d = 0; d < 64; d++) acc += q[i][d] * k[j][d];
        int yi = i >> 2, xi = i & 3, yj = j >> 2, xj = j & 3;
        int idx = (yi - yj + 3) * 7 + (xi - xj + 3);
        acc += rpb[idx * NHEADS + head];
        if (cnt[i] != cnt[j]) acc -= 100.0f;
        s[i][j] = acc;
    }
    __syncthreads();

    // Softmax per row (16 threads, one row each)
    if (t < 16) {
        float m = -1e30f;
        #pragma unroll
        for (int j = 0; j < 16; j++) m = fmaxf(m, s[t][j]);
        float p[16], sum = 0.0f;
        #pragma unroll
        for (int j = 0; j < 16; j++) { p[j] = __expf(s[t][j] - m); sum += p[j]; }
        float inv = 1.0f / sum;
        #pragma unroll
        for (int j = 0; j < 16; j++) s[t][j] = p[j] * inv;
    }
    __syncthreads();

    // O = P @ V ; thread covers (row i, 8 dims)
    int i  = t >> 3;
    int d0 = (t & 7) * 8;
    float acc[8];
    #pragma unroll
    for (int dd = 0; dd < 8; dd++) acc[dd] = 0.0f;
    #pragma unroll
    for (int j = 0; j < 16; j++) {
        float p = s[i][j];
        #pragma unroll
        for (int dd = 0; dd < 8; dd++) acc[dd] += p * v[j][d0 + dd];
    }
    float* op = g_ow + (size_t)(win * 16 + i) * CDIM + head * HDIM + d0;
    #pragma unroll
    for (int dd = 0; dd < 8; dd++) op[dd] = acc[dd];
}

// Tiny trampolines so host code can pass the scratch buffers without
// cudaGetSymbolAddress: kernels reference globals directly.
__global__ void ln1_entry(const float* x, const float* g1, const float* b1)
{
    // forwarding not used; see launch below
}

// ---------------------------------------------------------------------------
// Launch
// ---------------------------------------------------------------------------
template <bool GATHER>
static void launch_ln(const float* src, const float* gamma, const float* beta,
                      float* dst)
{
    ln_kernel<GATHER><<<ROWS, 128>>>(src, gamma, beta, dst);
}

extern "C" void kernel_launch(void* const* d_in, const int* in_sizes, int n_in,
                              void* d_out, int out_size)
{
    const float* x      = (const float*)d_in[0];
    const float* g1     = (const float*)d_in[1];
    const float* beta1  = (const float*)d_in[2];
    const float* w_qkv  = (const float*)d_in[3];
    const float* b_qkv  = (const float*)d_in[4];
    const float* rpb    = (const float*)d_in[5];
    const float* w_proj = (const float*)d_in[6];
    const float* b_proj = (const float*)d_in[7];
    const float* g2     = (const float*)d_in[8];
    const float* beta2  = (const float*)d_in[9];
    const float* w1     = (const float*)d_in[10];
    const float* b1     = (const float*)d_in[11];
    const float* w2     = (const float*)d_in[12];
    const float* b2     = (const float*)d_in[13];
    float* out = (float*)d_out;

    // Device-global scratch addresses (resolved host-side once per call;
    // cudaGetSymbolAddress is not a stream op and is capture-safe)
    float *xw, *qkv, *ow, *x2, *h2, *m1;
    cudaGetSymbolAddress((void**)&xw,  g_xw);
    cudaGetSymbolAddress((void**)&qkv, g_qkv);
    cudaGetSymbolAddress((void**)&ow,  g_ow);
    cudaGetSymbolAddress((void**)&x2,  g_x2);
    cudaGetSymbolAddress((void**)&h2,  g_h2);
    cudaGetSymbolAddress((void**)&m1,  g_m1);

    // 1. LN1 + cyclic shift + window partition  -> g_xw [32768, 512]
    ln_kernel<true><<<ROWS, 128>>>(x, g1, beta1, xw);

    // 2. QKV = xw @ w_qkv^T + b_qkv  -> g_qkv [32768, 1536]
    sgemm_kernel<0><<<dim3(1536/128, ROWS/128), 256>>>(xw, w_qkv, b_qkv, nullptr,
                                                       qkv, ROWS, 1536, CDIM);

    // 3. Windowed attention -> g_ow [32768, 512]
    attn_kernel<<<NWINDOWS * NHEADS, 128>>>(rpb);

    // 4. Proj + window-reverse + un-shift + residual(x)  -> g_x2 (token layout)
    sgemm_kernel<3><<<dim3(CDIM/128, ROWS/128), 256>>>(ow, w_proj, b_proj, x,
                                                       x2, ROWS, CDIM, CDIM);

    // 5. LN2 -> g_h2
    ln_kernel<false><<<ROWS, 128>>>(x2, g2, beta2, h2);

    // 6. FC1 + GELU -> g_m1 [32768, 1024]
    sgemm_kernel<1><<<dim3(FDIM/128, ROWS/128), 256>>>(h2, w1, b1, nullptr,
                                                       m1, ROWS, FDIM, CDIM);

    // 7. FC2 + residual(g_x2) -> d_out
    sgemm_kernel<2><<<dim3(CDIM/128, ROWS/128), 256>>>(m1, w2, b2, x2,
                                                       out, ROWS, CDIM, FDIM);
}

// round 5
// speedup vs baseline: 3.5718x; 3.5718x over previous
#include <cuda_runtime.h>
#include <cstdint>
#include <math.h>

// ---------------------------------------------------------------------------
// SwinTLayer: B=4, H=64, W=128, C=512, F=1024, NH=8, hd=64, WS=4, SS=2
// ---------------------------------------------------------------------------

#define BATCH   4
#define IMH     64
#define IMW     128
#define CDIM    512
#define LTOK    (IMH*IMW)            // 8192
#define NHEADS  8
#define HDIM    64
#define NWINDOWS 2048
#define ROWS    (NWINDOWS*16)         // 32768
#define FDIM    1024

// Scratch (device globals; cudaMalloc forbidden)
__device__ __align__(1024) float g_xw [ (size_t)ROWS*CDIM ];
__device__ __align__(1024) float g_qkv[ (size_t)ROWS*3*CDIM ];
__device__ __align__(1024) float g_ow [ (size_t)ROWS*CDIM ];
__device__ __align__(1024) float g_x2 [ (size_t)ROWS*CDIM ];
__device__ __align__(1024) float g_h2 [ (size_t)ROWS*CDIM ];
__device__ __align__(1024) float g_m1 [ (size_t)ROWS*FDIM ];
// tf32-rounded weight copies
__device__ __align__(1024) float g_wqkv[ 1536*512 ];
__device__ __align__(1024) float g_wproj[ 512*512 ];
__device__ __align__(1024) float g_w1  [ 1024*512 ];
__device__ __align__(1024) float g_w2  [ 512*1024 ];

// ---------------------------------------------------------------------------
// helpers
// ---------------------------------------------------------------------------
__device__ __forceinline__ float tf32r(float x) {
    uint32_t u;
    asm volatile("cvt.rna.tf32.f32 %0, %1;" : "=r"(u) : "f"(x));
    return __uint_as_float(u);
}

__device__ __forceinline__ uint32_t smem_u32(const void* p) {
    return (uint32_t)__cvta_generic_to_shared(p);
}

#define CP_ASYNC16(dst, src) \
    asm volatile("cp.async.cg.shared.global [%0], [%1], 16;" :: "r"(dst), "l"(src))
#define CP_COMMIT()  asm volatile("cp.async.commit_group;")
#define CP_WAIT1()   asm volatile("cp.async.wait_group 1;")

// m16n8k8 tf32 HMMA (legacy warp-level path; works on plain sm_103 target)
__device__ __forceinline__ void hmma_tf32(float* c,
                                          uint32_t a0, uint32_t a1, uint32_t a2, uint32_t a3,
                                          uint32_t b0, uint32_t b1)
{
    asm volatile(
        "mma.sync.aligned.m16n8k8.row.col.f32.tf32.tf32.f32 "
        "{%0,%1,%2,%3}, {%4,%5,%6,%7}, {%8,%9}, {%0,%1,%2,%3};"
        : "+f"(c[0]), "+f"(c[1]), "+f"(c[2]), "+f"(c[3])
        : "r"(a0), "r"(a1), "r"(a2), "r"(a3), "r"(b0), "r"(b1));
}

// window-row -> token-row map (shift + window partition; same gather/scatter)
__device__ __forceinline__ int swin_token(int r)
{
    int win   = r >> 4;
    int n     = r & 15;
    int b     = win >> 9;
    int local = win & 511;
    int wi    = local >> 5;
    int wj    = local & 31;
    int h     = (wi * 4 + (n >> 2) + 2) & (IMH - 1);
    int w     = (wj * 4 + (n & 3) + 2) & (IMW - 1);
    return b * LTOK + h * IMW + w;
}

// ---------------------------------------------------------------------------
// weight rounding to tf32 (unbiased rna)
// ---------------------------------------------------------------------------
__global__ void round_w_kernel(const float* __restrict__ a, const float* __restrict__ b,
                               const float* __restrict__ c, const float* __restrict__ d)
{
    int i = blockIdx.x * blockDim.x + threadIdx.x;
    int stride = gridDim.x * blockDim.x;
    for (int t = i; t < 1536*512; t += stride) g_wqkv[t]  = tf32r(a[t]);
    for (int t = i; t < 512*512;  t += stride) g_wproj[t] = tf32r(b[t]);
    for (int t = i; t < 1024*512; t += stride) g_w1[t]    = tf32r(c[t]);
    for (int t = i; t < 512*1024; t += stride) g_w2[t]    = tf32r(d[t]);
}

// ---------------------------------------------------------------------------
// LayerNorm (C=512), 128 threads, float4/thread. GATHER: swin gather from x.
// Output rounded to tf32 (feeds MMA).
// ---------------------------------------------------------------------------
template <bool GATHER>
__global__ void ln_kernel(const float* __restrict__ src,
                          const float* __restrict__ gamma,
                          const float* __restrict__ beta,
                          float* __restrict__ dst)
{
    int r    = blockIdx.x;
    int srow = GATHER ? swin_token(r) : r;
    float4 v = ((const float4*)(src + (size_t)srow * CDIM))[threadIdx.x];

    float s  = v.x + v.y + v.z + v.w;
    float sq = v.x*v.x + v.y*v.y + v.z*v.z + v.w*v.w;
    #pragma unroll
    for (int o = 16; o; o >>= 1) {
        s  += __shfl_xor_sync(0xffffffffu, s,  o);
        sq += __shfl_xor_sync(0xffffffffu, sq, o);
    }
    __shared__ float ss[4], ssq[4];
    int warp = threadIdx.x >> 5;
    if ((threadIdx.x & 31) == 0) { ss[warp] = s; ssq[warp] = sq; }
    __syncthreads();
    s  = ss[0] + ss[1] + ss[2] + ss[3];
    sq = ssq[0] + ssq[1] + ssq[2] + ssq[3];

    float mean = s * (1.0f / CDIM);
    float var  = sq * (1.0f / CDIM) - mean * mean;
    float rstd = rsqrtf(var + 1e-5f);

    float4 gv = ((const float4*)gamma)[threadIdx.x];
    float4 bv = ((const float4*)beta)[threadIdx.x];
    float4 o;
    o.x = tf32r((v.x - mean) * rstd * gv.x + bv.x);
    o.y = tf32r((v.y - mean) * rstd * gv.y + bv.y);
    o.z = tf32r((v.z - mean) * rstd * gv.z + bv.z);
    o.w = tf32r((v.w - mean) * rstd * gv.w + bv.w);
    ((float4*)(dst + (size_t)r * CDIM))[threadIdx.x] = o;
}

// ---------------------------------------------------------------------------
// HMMA tf32 GEMM: C[M,N] = A[M,K] @ B[N,K]^T (+bias, epilogue).
// CTA tile 128x256, BK=32 floats, 256 threads (8 warps, each 64x64),
// 3-stage cp.async pipeline, XOR-swizzled SMEM (conflict-free fragments).
// EPI: 0 bias | 1 bias+GELU+tf32round | 2 bias+aux[r,c] | 3 bias+swin scatter+aux
// ---------------------------------------------------------------------------
#define BM 128
#define BN 256
#define BK 32
#define NSTAGES 3
#define STAGE_FLOATS ((BM + BN) * BK)           // 12288 floats = 48KB
#define STAGE_BYTES  (STAGE_FLOATS * 4)
#define DYN_BYTES    (NSTAGES * STAGE_BYTES)    // 147456

template <int EPI>
__global__ void __launch_bounds__(256, 1)
mma_gemm(const float* __restrict__ A, const float* __restrict__ Bm,
         const float* __restrict__ bias, const float* __restrict__ aux,
         float* __restrict__ C, int Nn, int K)
{
    extern __shared__ char dyn[];
    uint32_t smem_base = smem_u32(dyn);

    int tid  = threadIdx.x;
    int wid  = tid >> 5;
    int lane = tid & 31;
    int rA   = lane >> 2;       // 0..7
    int cA   = lane & 3;        // 0..3

    int wm = wid & 1;           // 2 warp rows
    int wn = wid >> 1;          // 4 warp cols
    int m0 = wm * 64;
    int n0 = wn * 64;

    int row0 = blockIdx.y * BM;
    int col0 = blockIdx.x * BN;
    int S    = K >> 5;          // K-slices of 32 floats

    const float* Abase = A  + (size_t)row0 * K;
    const float* Bbase = Bm + (size_t)col0 * K;

    // swizzled per-thread fragment offsets within a 128B (32-float) row:
    // float index = row*32 + swz[chunk], chunk = k>>2 (0..7)
    uint32_t swz[8];
    #pragma unroll
    for (int c = 0; c < 8; c++) swz[c] = (uint32_t)(((c ^ rA) << 2) + cA);

    // ---- async tile loader: 12 cp.async (16B) per thread per stage ----
    auto load_slice = [&](int ks, int st) {
        uint32_t sA = smem_base + st * STAGE_BYTES;
        uint32_t sB = sA + BM * BK * 4;
        const float* Ap = Abase + ks * BK;
        const float* Bp = Bbase + ks * BK;
        #pragma unroll
        for (int p = 0; p < 4; p++) {                  // A: 1024 chunks
            int idx = p * 256 + tid;
            int row = idx >> 3, ch = idx & 7;
            CP_ASYNC16(sA + (uint32_t)(row * 128 + ((ch ^ (row & 7)) * 16)),
                       Ap + (size_t)row * K + ch * 4);
        }
        #pragma unroll
        for (int p = 0; p < 8; p++) {                  // B: 2048 chunks
            int idx = p * 256 + tid;
            int row = idx >> 3, ch = idx & 7;
            CP_ASYNC16(sB + (uint32_t)(row * 128 + ((ch ^ (row & 7)) * 16)),
                       Bp + (size_t)row * K + ch * 4);
        }
    };

    float acc[4][8][4];
    #pragma unroll
    for (int i = 0; i < 4; i++)
        #pragma unroll
        for (int j = 0; j < 8; j++)
            #pragma unroll
            for (int q = 0; q < 4; q++) acc[i][j][q] = 0.0f;

    load_slice(0, 0); CP_COMMIT();
    load_slice(1, 1); CP_COMMIT();

    for (int ks = 0; ks < S; ks++) {
        int st = ks % NSTAGES;
        CP_WAIT1();
        __syncthreads();

        const uint32_t* sA = (const uint32_t*)(dyn + st * STAGE_BYTES);
        const uint32_t* sB = sA + BM * BK;

        #pragma unroll
        for (int kt = 0; kt < 4; kt++) {
            uint32_t af[4][4];
            #pragma unroll
            for (int mt = 0; mt < 4; mt++) {
                int r0 = m0 + mt * 16 + rA;
                af[mt][0] = sA[(r0    ) * 32 + swz[kt*2  ]];
                af[mt][1] = sA[(r0 + 8) * 32 + swz[kt*2  ]];
                af[mt][2] = sA[(r0    ) * 32 + swz[kt*2+1]];
                af[mt][3] = sA[(r0 + 8) * 32 + swz[kt*2+1]];
            }
            uint32_t bf[8][2];
            #pragma unroll
            for (int nt = 0; nt < 8; nt++) {
                int rb = n0 + nt * 8 + rA;
                bf[nt][0] = sB[rb * 32 + swz[kt*2  ]];
                bf[nt][1] = sB[rb * 32 + swz[kt*2+1]];
            }
            #pragma unroll
            for (int mt = 0; mt < 4; mt++)
                #pragma unroll
                for (int nt = 0; nt < 8; nt++)
                    hmma_tf32(acc[mt][nt], af[mt][0], af[mt][1], af[mt][2], af[mt][3],
                              bf[nt][0], bf[nt][1]);
        }

        if (ks + 2 < S) load_slice(ks + 2, (ks + 2) % NSTAGES);
        CP_COMMIT();
    }

    // ---- epilogue: direct float2 stores ----
    #pragma unroll
    for (int mt = 0; mt < 4; mt++) {
        #pragma unroll
        for (int half = 0; half < 2; half++) {
            int grow = row0 + m0 + mt * 16 + half * 8 + rA;
            int tt   = (EPI == 3) ? swin_token(grow) : grow;
            #pragma unroll
            for (int nt = 0; nt < 8; nt++) {
                int col = col0 + n0 + nt * 8 + cA * 2;
                float v0 = acc[mt][nt][half * 2 + 0] + bias[col];
                float v1 = acc[mt][nt][half * 2 + 1] + bias[col + 1];
                if (EPI == 1) {
                    v0 = tf32r(0.5f * v0 * (1.0f + erff(v0 * 0.70710678118654752f)));
                    v1 = tf32r(0.5f * v1 * (1.0f + erff(v1 * 0.70710678118654752f)));
                } else if (EPI == 2) {
                    float2 ax = *(const float2*)(aux + (size_t)grow * Nn + col);
                    v0 += ax.x; v1 += ax.y;
                } else if (EPI == 3) {
                    float2 ax = *(const float2*)(aux + (size_t)tt * CDIM + col);
                    v0 += ax.x; v1 += ax.y;
                }
                float2 o = make_float2(v0, v1);
                if (EPI == 3) *(float2*)(C + (size_t)tt * CDIM + col) = o;
                else          *(float2*)(C + (size_t)grow * Nn + col) = o;
            }
        }
    }
}

// ---------------------------------------------------------------------------
// Windowed attention: one block per (window, head). Exact fp32.
// Output rounded to tf32 (feeds proj MMA).
// ---------------------------------------------------------------------------
__global__ void attn_kernel(const float* __restrict__ rpb)
{
    __shared__ float q[16][64], k[16][64], v[16][64];
    __shared__ float s[16][16];
    __shared__ int   cnt[16];

    int blk  = blockIdx.x;
    int win  = blk >> 3;
    int head = blk & 7;
    int t    = threadIdx.x;

    int local = win & 511;
    int wi = local >> 5, wj = local & 31;
    if (t < 16) {
        int hs = wi * 4 + (t >> 2);
        int ws = wj * 4 + (t & 3);
        int rh = hs < (IMH - 4) ? 0 : (hs < (IMH - 2) ? 1 : 2);
        int rw = ws < (IMW - 4) ? 0 : (ws < (IMW - 2) ? 1 : 2);
        cnt[t] = rh * 3 + rw;
    }

    size_t base = (size_t)(win * 16) * (3 * CDIM) + head * HDIM;
    #pragma unroll
    for (int rep = 0; rep < 2; rep++) {
        int slot = t + rep * 128;
        int n  = slot >> 4;
        int d4 = (slot & 15) * 4;
        size_t roff = base + (size_t)n * (3 * CDIM) + d4;
        float4 qv = *(const float4*)(g_qkv + roff);
        float4 kv = *(const float4*)(g_qkv + roff + CDIM);
        float4 vv = *(const float4*)(g_qkv + roff + 2 * CDIM);
        q[n][d4+0] = qv.x * 0.125f; q[n][d4+1] = qv.y * 0.125f;
        q[n][d4+2] = qv.z * 0.125f; q[n][d4+3] = qv.w * 0.125f;
        k[n][d4+0] = kv.x; k[n][d4+1] = kv.y; k[n][d4+2] = kv.z; k[n][d4+3] = kv.w;
        v[n][d4+0] = vv.x; v[n][d4+1] = vv.y; v[n][d4+2] = vv.z; v[n][d4+3] = vv.w;
    }
    __syncthreads();

    #pragma unroll
    for (int rep = 0; rep < 2; rep++) {
        int e = t + rep * 128;
        int i = e >> 4, j = e & 15;
        float acc = 0.0f;
        #pragma unroll
        for (int d = 0; d < 64; d++) acc += q[i][d] * k[j][d];
        int yi = i >> 2, xi = i & 3, yj = j >> 2, xj = j & 3;
        int idx = (yi - yj + 3) * 7 + (xi - xj + 3);
        acc += rpb[idx * NHEADS + head];
        if (cnt[i] != cnt[j]) acc -= 100.0f;
        s[i][j] = acc;
    }
    __syncthreads();

    if (t < 16) {
        float m = -1e30f;
        #pragma unroll
        for (int j = 0; j < 16; j++) m = fmaxf(m, s[t][j]);
        float p[16], sum = 0.0f;
        #pragma unroll
        for (int j = 0; j < 16; j++) { p[j] = __expf(s[t][j] - m); sum += p[j]; }
        float inv = 1.0f / sum;
        #pragma unroll
        for (int j = 0; j < 16; j++) s[t][j] = p[j] * inv;
    }
    __syncthreads();

    int i  = t >> 3;
    int d0 = (t & 7) * 8;
    float acc[8];
    #pragma unroll
    for (int dd = 0; dd < 8; dd++) acc[dd] = 0.0f;
    #pragma unroll
    for (int j = 0; j < 16; j++) {
        float p = s[i][j];
        #pragma unroll
        for (int dd = 0; dd < 8; dd++) acc[dd] += p * v[j][d0 + dd];
    }
    float* op = g_ow + (size_t)(win * 16 + i) * CDIM + head * HDIM + d0;
    #pragma unroll
    for (int dd = 0; dd < 8; dd++) op[dd] = tf32r(acc[dd]);
}

// ---------------------------------------------------------------------------
// Launch
// ---------------------------------------------------------------------------
extern "C" void kernel_launch(void* const* d_in, const int* in_sizes, int n_in,
                              void* d_out, int out_size)
{
    const float* x      = (const float*)d_in[0];
    const float* g1     = (const float*)d_in[1];
    const float* beta1  = (const float*)d_in[2];
    const float* w_qkv  = (const float*)d_in[3];
    const float* b_qkv  = (const float*)d_in[4];
    const float* rpb    = (const float*)d_in[5];
    const float* w_proj = (const float*)d_in[6];
    const float* b_proj = (const float*)d_in[7];
    const float* g2     = (const float*)d_in[8];
    const float* beta2  = (const float*)d_in[9];
    const float* w1     = (const float*)d_in[10];
    const float* b1     = (const float*)d_in[11];
    const float* w2     = (const float*)d_in[12];
    const float* b2     = (const float*)d_in[13];
    float* out = (float*)d_out;

    float *xw, *ow, *x2, *h2, *m1, *qkv;
    float *wq, *wp, *wa, *wb;
    cudaGetSymbolAddress((void**)&xw,  g_xw);
    cudaGetSymbolAddress((void**)&qkv, g_qkv);
    cudaGetSymbolAddress((void**)&ow,  g_ow);
    cudaGetSymbolAddress((void**)&x2,  g_x2);
    cudaGetSymbolAddress((void**)&h2,  g_h2);
    cudaGetSymbolAddress((void**)&m1,  g_m1);
    cudaGetSymbolAddress((void**)&wq,  g_wqkv);
    cudaGetSymbolAddress((void**)&wp,  g_wproj);
    cudaGetSymbolAddress((void**)&wa,  g_w1);
    cudaGetSymbolAddress((void**)&wb,  g_w2);

    cudaFuncSetAttribute(mma_gemm<0>, cudaFuncAttributeMaxDynamicSharedMemorySize, DYN_BYTES);
    cudaFuncSetAttribute(mma_gemm<1>, cudaFuncAttributeMaxDynamicSharedMemorySize, DYN_BYTES);
    cudaFuncSetAttribute(mma_gemm<2>, cudaFuncAttributeMaxDynamicSharedMemorySize, DYN_BYTES);
    cudaFuncSetAttribute(mma_gemm<3>, cudaFuncAttributeMaxDynamicSharedMemorySize, DYN_BYTES);

    // 0. round weights to tf32
    round_w_kernel<<<148, 256>>>(w_qkv, w_proj, w1, w2);

    // 1. LN1 + shift + window partition -> g_xw (tf32-rounded)
    ln_kernel<true><<<ROWS, 128>>>(x, g1, beta1, xw);

    // 2. QKV: [32768,1536] = xw @ wqkv^T
    mma_gemm<0><<<dim3(1536/BN, ROWS/BM), 256, DYN_BYTES>>>(xw, wq, b_qkv, nullptr, qkv, 1536, 512);

    // 3. attention -> g_ow (tf32-rounded)
    attn_kernel<<<NWINDOWS * NHEADS, 128>>>(rpb);

    // 4. proj + window reverse + unshift + residual(x) -> g_x2
    mma_gemm<3><<<dim3(512/BN, ROWS/BM), 256, DYN_BYTES>>>(ow, wp, b_proj, x, x2, 512, 512);

    // 5. LN2 -> g_h2 (tf32-rounded)
    ln_kernel<false><<<ROWS, 128>>>(x2, g2, beta2, h2);

    // 6. FC1 + GELU -> g_m1 (tf32-rounded)
    mma_gemm<1><<<dim3(1024/BN, ROWS/BM), 256, DYN_BYTES>>>(h2, wa, b1, nullptr, m1, 1024, 512);

    // 7. FC2 + residual(g_x2) -> out
    mma_gemm<2><<<dim3(512/BN, ROWS/BM), 256, DYN_BYTES>>>(m1, wb, b2, x2, out, 512, 1024);
}

// round 6
// speedup vs baseline: 4.2727x; 1.1962x over previous
#include <cuda_runtime.h>
#include <cstdint>
#include <math.h>

// ---------------------------------------------------------------------------
// SwinTLayer: B=4, H=64, W=128, C=512, F=1024, NH=8, hd=64, WS=4, SS=2
// ---------------------------------------------------------------------------

#define BATCH   4
#define IMH     64
#define IMW     128
#define CDIM    512
#define LTOK    (IMH*IMW)            // 8192
#define NHEADS  8
#define HDIM    64
#define NWINDOWS 2048
#define ROWS    (NWINDOWS*16)         // 32768
#define FDIM    1024

// Scratch (device globals; cudaMalloc forbidden)
__device__ __align__(1024) float g_xw [ (size_t)ROWS*CDIM ];
__device__ __align__(1024) float g_qkv[ (size_t)ROWS*3*CDIM ];
__device__ __align__(1024) float g_ow [ (size_t)ROWS*CDIM ];
__device__ __align__(1024) float g_x2 [ (size_t)ROWS*CDIM ];
__device__ __align__(1024) float g_h2 [ (size_t)ROWS*CDIM ];
__device__ __align__(1024) float g_m1 [ (size_t)ROWS*FDIM ];
// tf32-rounded weight copies
__device__ __align__(1024) float g_wqkv[ 1536*512 ];
__device__ __align__(1024) float g_wproj[ 512*512 ];
__device__ __align__(1024) float g_w1  [ 1024*512 ];
__device__ __align__(1024) float g_w2  [ 512*1024 ];

// ---------------------------------------------------------------------------
// helpers
// ---------------------------------------------------------------------------
__device__ __forceinline__ float tf32r(float x) {
    uint32_t u;
    asm volatile("cvt.rna.tf32.f32 %0, %1;" : "=r"(u) : "f"(x));
    return __uint_as_float(u);
}
__device__ __forceinline__ uint32_t tf32u(float x) {
    uint32_t u;
    asm volatile("cvt.rna.tf32.f32 %0, %1;" : "=r"(u) : "f"(x));
    return u;
}

__device__ __forceinline__ uint32_t smem_u32(const void* p) {
    return (uint32_t)__cvta_generic_to_shared(p);
}

#define CP_ASYNC16(dst, src) \
    asm volatile("cp.async.cg.shared.global [%0], [%1], 16;" :: "r"(dst), "l"(src))
#define CP_COMMIT()  asm volatile("cp.async.commit_group;")
#define CP_WAIT1()   asm volatile("cp.async.wait_group 1;")

// m16n8k8 tf32 HMMA (legacy warp-level path; works on plain sm_103 target)
__device__ __forceinline__ void hmma_tf32(float* c,
                                          uint32_t a0, uint32_t a1, uint32_t a2, uint32_t a3,
                                          uint32_t b0, uint32_t b1)
{
    asm volatile(
        "mma.sync.aligned.m16n8k8.row.col.f32.tf32.tf32.f32 "
        "{%0,%1,%2,%3}, {%4,%5,%6,%7}, {%8,%9}, {%0,%1,%2,%3};"
        : "+f"(c[0]), "+f"(c[1]), "+f"(c[2]), "+f"(c[3])
        : "r"(a0), "r"(a1), "r"(a2), "r"(a3), "r"(b0), "r"(b1));
}

// window-row -> token-row map (shift + window partition; same gather/scatter)
__device__ __forceinline__ int swin_token(int r)
{
    int win   = r >> 4;
    int n     = r & 15;
    int b     = win >> 9;
    int local = win & 511;
    int wi    = local >> 5;
    int wj    = local & 31;
    int h     = (wi * 4 + (n >> 2) + 2) & (IMH - 1);
    int w     = (wj * 4 + (n & 3) + 2) & (IMW - 1);
    return b * LTOK + h * IMW + w;
}

// ---------------------------------------------------------------------------
// weight rounding to tf32 (unbiased rna)
// ---------------------------------------------------------------------------
__global__ void round_w_kernel(const float* __restrict__ a, const float* __restrict__ b,
                               const float* __restrict__ c, const float* __restrict__ d)
{
    int i = blockIdx.x * blockDim.x + threadIdx.x;
    int stride = gridDim.x * blockDim.x;
    for (int t = i; t < 1536*512; t += stride) g_wqkv[t]  = tf32r(a[t]);
    for (int t = i; t < 512*512;  t += stride) g_wproj[t] = tf32r(b[t]);
    for (int t = i; t < 1024*512; t += stride) g_w1[t]    = tf32r(c[t]);
    for (int t = i; t < 512*1024; t += stride) g_w2[t]    = tf32r(d[t]);
}

// ---------------------------------------------------------------------------
// LayerNorm (C=512), 128 threads, float4/thread. GATHER: swin gather from x.
// Output rounded to tf32 (feeds MMA).
// ---------------------------------------------------------------------------
template <bool GATHER>
__global__ void ln_kernel(const float* __restrict__ src,
                          const float* __restrict__ gamma,
                          const float* __restrict__ beta,
                          float* __restrict__ dst)
{
    int r    = blockIdx.x;
    int srow = GATHER ? swin_token(r) : r;
    float4 v = ((const float4*)(src + (size_t)srow * CDIM))[threadIdx.x];

    float s  = v.x + v.y + v.z + v.w;
    float sq = v.x*v.x + v.y*v.y + v.z*v.z + v.w*v.w;
    #pragma unroll
    for (int o = 16; o; o >>= 1) {
        s  += __shfl_xor_sync(0xffffffffu, s,  o);
        sq += __shfl_xor_sync(0xffffffffu, sq, o);
    }
    __shared__ float ss[4], ssq[4];
    int warp = threadIdx.x >> 5;
    if ((threadIdx.x & 31) == 0) { ss[warp] = s; ssq[warp] = sq; }
    __syncthreads();
    s  = ss[0] + ss[1] + ss[2] + ss[3];
    sq = ssq[0] + ssq[1] + ssq[2] + ssq[3];

    float mean = s * (1.0f / CDIM);
    float var  = sq * (1.0f / CDIM) - mean * mean;
    float rstd = rsqrtf(var + 1e-5f);

    float4 gv = ((const float4*)gamma)[threadIdx.x];
    float4 bv = ((const float4*)beta)[threadIdx.x];
    float4 o;
    o.x = tf32r((v.x - mean) * rstd * gv.x + bv.x);
    o.y = tf32r((v.y - mean) * rstd * gv.y + bv.y);
    o.z = tf32r((v.z - mean) * rstd * gv.z + bv.z);
    o.w = tf32r((v.w - mean) * rstd * gv.w + bv.w);
    ((float4*)(dst + (size_t)r * CDIM))[threadIdx.x] = o;
}

// ---------------------------------------------------------------------------
// HMMA tf32 GEMM: C[M,N] = A[M,K] @ B[N,K]^T (+bias, epilogue).
// CTA tile 128x128, BK=32, 256 threads (8 warps, each 64x32),
// 3-stage cp.async pipeline (96KB -> 2 CTAs/SM), XOR-swizzled SMEM.
// EPI: 0 bias | 1 bias+GELU+tf32round | 2 bias+aux[r,c] | 3 bias+swin scatter+aux
// ---------------------------------------------------------------------------
#define BM 128
#define BN 128
#define BK 32
#define NSTAGES 3
#define STAGE_FLOATS ((BM + BN) * BK)           // 8192 floats = 32KB
#define STAGE_BYTES  (STAGE_FLOATS * 4)
#define DYN_BYTES    (NSTAGES * STAGE_BYTES)    // 98304

template <int EPI>
__global__ void __launch_bounds__(256, 2)
mma_gemm(const float* __restrict__ A, const float* __restrict__ Bm,
         const float* __restrict__ bias, const float* __restrict__ aux,
         float* __restrict__ C, int Nn, int K)
{
    extern __shared__ char dyn[];
    uint32_t smem_base = smem_u32(dyn);

    int tid  = threadIdx.x;
    int wid  = tid >> 5;
    int lane = tid & 31;
    int rA   = lane >> 2;       // 0..7
    int cA   = lane & 3;        // 0..3

    int m0 = (wid & 1) * 64;    // 2 warp rows (64 each)
    int n0 = (wid >> 1) * 32;   // 4 warp cols (32 each)

    int row0 = blockIdx.y * BM;
    int col0 = blockIdx.x * BN;
    int S    = K >> 5;          // K-slices of 32 floats

    const float* Abase = A  + (size_t)row0 * K;
    const float* Bbase = Bm + (size_t)col0 * K;

    // swizzled per-thread fragment offsets within a 128B (32-float) row
    uint32_t swz[8];
    #pragma unroll
    for (int c = 0; c < 8; c++) swz[c] = (uint32_t)(((c ^ rA) << 2) + cA);

    // ---- async tile loader: 8 cp.async (16B) per thread per stage ----
    auto load_slice = [&](int ks, int st) {
        uint32_t sA = smem_base + st * STAGE_BYTES;
        uint32_t sB = sA + BM * BK * 4;
        const float* Ap = Abase + ks * BK;
        const float* Bp = Bbase + ks * BK;
        #pragma unroll
        for (int p = 0; p < 4; p++) {                  // A: 1024 chunks
            int idx = p * 256 + tid;
            int row = idx >> 3, ch = idx & 7;
            CP_ASYNC16(sA + (uint32_t)(row * 128 + ((ch ^ (row & 7)) * 16)),
                       Ap + (size_t)row * K + ch * 4);
        }
        #pragma unroll
        for (int p = 0; p < 4; p++) {                  // B: 1024 chunks
            int idx = p * 256 + tid;
            int row = idx >> 3, ch = idx & 7;
            CP_ASYNC16(sB + (uint32_t)(row * 128 + ((ch ^ (row & 7)) * 16)),
                       Bp + (size_t)row * K + ch * 4);
        }
    };

    float acc[4][4][4];
    #pragma unroll
    for (int i = 0; i < 4; i++)
        #pragma unroll
        for (int j = 0; j < 4; j++)
            #pragma unroll
            for (int q = 0; q < 4; q++) acc[i][j][q] = 0.0f;

    load_slice(0, 0); CP_COMMIT();
    load_slice(1, 1); CP_COMMIT();

    for (int ks = 0; ks < S; ks++) {
        int st = ks % NSTAGES;
        CP_WAIT1();
        __syncthreads();

        const uint32_t* sA = (const uint32_t*)(dyn + st * STAGE_BYTES);
        const uint32_t* sB = sA + BM * BK;

        #pragma unroll
        for (int kt = 0; kt < 4; kt++) {
            uint32_t af[4][4];
            #pragma unroll
            for (int mt = 0; mt < 4; mt++) {
                int r0 = m0 + mt * 16 + rA;
                af[mt][0] = sA[(r0    ) * 32 + swz[kt*2  ]];
                af[mt][1] = sA[(r0 + 8) * 32 + swz[kt*2  ]];
                af[mt][2] = sA[(r0    ) * 32 + swz[kt*2+1]];
                af[mt][3] = sA[(r0 + 8) * 32 + swz[kt*2+1]];
            }
            uint32_t bf[4][2];
            #pragma unroll
            for (int nt = 0; nt < 4; nt++) {
                int rb = n0 + nt * 8 + rA;
                bf[nt][0] = sB[rb * 32 + swz[kt*2  ]];
                bf[nt][1] = sB[rb * 32 + swz[kt*2+1]];
            }
            #pragma unroll
            for (int mt = 0; mt < 4; mt++)
                #pragma unroll
                for (int nt = 0; nt < 4; nt++)
                    hmma_tf32(acc[mt][nt], af[mt][0], af[mt][1], af[mt][2], af[mt][3],
                              bf[nt][0], bf[nt][1]);
        }

        if (ks + 2 < S) load_slice(ks + 2, (ks + 2) % NSTAGES);
        CP_COMMIT();
    }

    // ---- epilogue: direct float2 stores ----
    #pragma unroll
    for (int mt = 0; mt < 4; mt++) {
        #pragma unroll
        for (int half = 0; half < 2; half++) {
            int grow = row0 + m0 + mt * 16 + half * 8 + rA;
            int tt   = (EPI == 3) ? swin_token(grow) : grow;
            #pragma unroll
            for (int nt = 0; nt < 4; nt++) {
                int col = col0 + n0 + nt * 8 + cA * 2;
                float v0 = acc[mt][nt][half * 2 + 0] + bias[col];
                float v1 = acc[mt][nt][half * 2 + 1] + bias[col + 1];
                if (EPI == 1) {
                    v0 = tf32r(0.5f * v0 * (1.0f + erff(v0 * 0.70710678118654752f)));
                    v1 = tf32r(0.5f * v1 * (1.0f + erff(v1 * 0.70710678118654752f)));
                } else if (EPI == 2) {
                    float2 ax = *(const float2*)(aux + (size_t)grow * Nn + col);
                    v0 += ax.x; v1 += ax.y;
                } else if (EPI == 3) {
                    float2 ax = *(const float2*)(aux + (size_t)tt * CDIM + col);
                    v0 += ax.x; v1 += ax.y;
                }
                float2 o = make_float2(v0, v1);
                if (EPI == 3) *(float2*)(C + (size_t)tt * CDIM + col) = o;
                else          *(float2*)(C + (size_t)grow * Nn + col) = o;
            }
        }
    }
}

// ---------------------------------------------------------------------------
// Windowed attention via HMMA: one warp per (window, head).
// Block = 256 threads = 8 warps = 8 heads of one window. Grid = 2048.
// Fragments loaded straight from gmem (sector-efficient pairs).
// ---------------------------------------------------------------------------
__global__ void __launch_bounds__(256) attn_mma(const float* __restrict__ rpb)
{
    __shared__ __align__(16) float sp[8][16][18];   // P tiles, padded rows (72B)

    int win  = blockIdx.x;
    int head = threadIdx.x >> 5;
    int lane = threadIdx.x & 31;
    int rhi  = lane >> 2;       // 0..7
    int rlo  = lane & 3;        // 0..3

    const float* qb = g_qkv + (size_t)(win * 16) * 1536 + head * 64;
    const float* kb = qb + 512;
    const float* vb = qb + 1024;

    int local = win & 511;
    int wi = local >> 5, wj = local & 31;

    // region id of a window token (for the shifted-window mask)
    auto reg_of = [&](int tok) {
        int hs = wi * 4 + (tok >> 2);
        int ws = wj * 4 + (tok & 3);
        int rh = hs < (IMH - 4) ? 0 : (hs < (IMH - 2) ? 1 : 2);
        int rw = ws < (IMW - 4) ? 0 : (ws < (IMW - 2) ? 1 : 2);
        return rh * 3 + rw;
    };

    // ---- S = (Q*scale) K^T : two 16x8 n-tiles ----
    float s0[4] = {0,0,0,0}, s1[4] = {0,0,0,0};
    #pragma unroll
    for (int kt = 0; kt < 8; kt++) {
        int c = kt * 8 + rlo;
        uint32_t a0 = tf32u(qb[(size_t)rhi * 1536 + c] * 0.125f);
        uint32_t a1 = tf32u(qb[(size_t)(rhi + 8) * 1536 + c] * 0.125f);
        uint32_t a2 = tf32u(qb[(size_t)rhi * 1536 + c + 4] * 0.125f);
        uint32_t a3 = tf32u(qb[(size_t)(rhi + 8) * 1536 + c + 4] * 0.125f);
        uint32_t b0 = tf32u(kb[(size_t)rhi * 1536 + c]);
        uint32_t b1 = tf32u(kb[(size_t)rhi * 1536 + c + 4]);
        hmma_tf32(s0, a0, a1, a2, a3, b0, b1);
        b0 = tf32u(kb[(size_t)(rhi + 8) * 1536 + c]);
        b1 = tf32u(kb[(size_t)(rhi + 8) * 1536 + c + 4]);
        hmma_tf32(s1, a0, a1, a2, a3, b0, b1);
    }

    // ---- + rel-pos bias + shift mask ----
    int i0 = rhi, i1 = rhi + 8;
    int ri0 = reg_of(i0), ri1 = reg_of(i1);
    #pragma unroll
    for (int nt = 0; nt < 2; nt++) {
        float* s = nt ? s1 : s0;
        #pragma unroll
        for (int q = 0; q < 4; q++) {
            int i  = (q < 2) ? i0 : i1;
            int ri = (q < 2) ? ri0 : ri1;
            int j  = nt * 8 + 2 * rlo + (q & 1);
            int idx = ((i >> 2) - (j >> 2) + 3) * 7 + ((i & 3) - (j & 3) + 3);
            float b = __ldg(rpb + idx * NHEADS + head);
            s[q] += b + ((ri != reg_of(j)) ? -100.0f : 0.0f);
        }
    }

    // ---- softmax: rows i0 (regs 0,1) and i1 (regs 2,3), quad reduce ----
    float m0 = fmaxf(fmaxf(s0[0], s0[1]), fmaxf(s1[0], s1[1]));
    float m1 = fmaxf(fmaxf(s0[2], s0[3]), fmaxf(s1[2], s1[3]));
    m0 = fmaxf(m0, __shfl_xor_sync(~0u, m0, 1));
    m0 = fmaxf(m0, __shfl_xor_sync(~0u, m0, 2));
    m1 = fmaxf(m1, __shfl_xor_sync(~0u, m1, 1));
    m1 = fmaxf(m1, __shfl_xor_sync(~0u, m1, 2));
    s0[0] = __expf(s0[0] - m0); s0[1] = __expf(s0[1] - m0);
    s1[0] = __expf(s1[0] - m0); s1[1] = __expf(s1[1] - m0);
    s0[2] = __expf(s0[2] - m1); s0[3] = __expf(s0[3] - m1);
    s1[2] = __expf(s1[2] - m1); s1[3] = __expf(s1[3] - m1);
    float t0 = s0[0] + s0[1] + s1[0] + s1[1];
    float t1 = s0[2] + s0[3] + s1[2] + s1[3];
    t0 += __shfl_xor_sync(~0u, t0, 1); t0 += __shfl_xor_sync(~0u, t0, 2);
    t1 += __shfl_xor_sync(~0u, t1, 1); t1 += __shfl_xor_sync(~0u, t1, 2);
    float inv0 = 1.0f / t0, inv1 = 1.0f / t1;

    // ---- store P (tf32-rounded) to smem, convert to A-fragment layout ----
    #pragma unroll
    for (int nt = 0; nt < 2; nt++) {
        const float* s = nt ? s1 : s0;
        *(float2*)&sp[head][i0][nt * 8 + 2 * rlo] =
            make_float2(tf32r(s[0] * inv0), tf32r(s[1] * inv0));
        *(float2*)&sp[head][i1][nt * 8 + 2 * rlo] =
            make_float2(tf32r(s[2] * inv1), tf32r(s[3] * inv1));
    }
    __syncwarp();

    uint32_t pa[2][4];
    #pragma unroll
    for (int kt = 0; kt < 2; kt++) {
        pa[kt][0] = __float_as_uint(sp[head][i0][kt * 8 + rlo]);
        pa[kt][1] = __float_as_uint(sp[head][i1][kt * 8 + rlo]);
        pa[kt][2] = __float_as_uint(sp[head][i0][kt * 8 + rlo + 4]);
        pa[kt][3] = __float_as_uint(sp[head][i1][kt * 8 + rlo + 4]);
    }

    // ---- O = P V : 8 n-tiles over hd=64 ----
    float* ob = g_ow + (size_t)(win * 16) * CDIM + head * 64;
    #pragma unroll
    for (int nt = 0; nt < 8; nt++) {
        float o[4] = {0, 0, 0, 0};
        #pragma unroll
        for (int kt = 0; kt < 2; kt++) {
            uint32_t b0 = tf32u(vb[(size_t)(kt * 8 + rlo) * 1536 + nt * 8 + rhi]);
            uint32_t b1 = tf32u(vb[(size_t)(kt * 8 + rlo + 4) * 1536 + nt * 8 + rhi]);
            hmma_tf32(o, pa[kt][0], pa[kt][1], pa[kt][2], pa[kt][3], b0, b1);
        }
        int col = nt * 8 + 2 * rlo;
        *(float2*)&ob[(size_t)i0 * CDIM + col] = make_float2(tf32r(o[0]), tf32r(o[1]));
        *(float2*)&ob[(size_t)i1 * CDIM + col] = make_float2(tf32r(o[2]), tf32r(o[3]));
    }
}

// ---------------------------------------------------------------------------
// Launch
// ---------------------------------------------------------------------------
extern "C" void kernel_launch(void* const* d_in, const int* in_sizes, int n_in,
                              void* d_out, int out_size)
{
    const float* x      = (const float*)d_in[0];
    const float* g1     = (const float*)d_in[1];
    const float* beta1  = (const float*)d_in[2];
    const float* w_qkv  = (const float*)d_in[3];
    const float* b_qkv  = (const float*)d_in[4];
    const float* rpb    = (const float*)d_in[5];
    const float* w_proj = (const float*)d_in[6];
    const float* b_proj = (const float*)d_in[7];
    const float* g2     = (const float*)d_in[8];
    const float* beta2  = (const float*)d_in[9];
    const float* w1     = (const float*)d_in[10];
    const float* b1     = (const float*)d_in[11];
    const float* w2     = (const float*)d_in[12];
    const float* b2     = (const float*)d_in[13];
    float* out = (float*)d_out;

    float *xw, *ow, *x2, *h2, *m1, *qkv;
    float *wq, *wp, *wa, *wb;
    cudaGetSymbolAddress((void**)&xw,  g_xw);
    cudaGetSymbolAddress((void**)&qkv, g_qkv);
    cudaGetSymbolAddress((void**)&ow,  g_ow);
    cudaGetSymbolAddress((void**)&x2,  g_x2);
    cudaGetSymbolAddress((void**)&h2,  g_h2);
    cudaGetSymbolAddress((void**)&m1,  g_m1);
    cudaGetSymbolAddress((void**)&wq,  g_wqkv);
    cudaGetSymbolAddress((void**)&wp,  g_wproj);
    cudaGetSymbolAddress((void**)&wa,  g_w1);
    cudaGetSymbolAddress((void**)&wb,  g_w2);

    cudaFuncSetAttribute(mma_gemm<0>, cudaFuncAttributeMaxDynamicSharedMemorySize, DYN_BYTES);
    cudaFuncSetAttribute(mma_gemm<1>, cudaFuncAttributeMaxDynamicSharedMemorySize, DYN_BYTES);
    cudaFuncSetAttribute(mma_gemm<2>, cudaFuncAttributeMaxDynamicSharedMemorySize, DYN_BYTES);
    cudaFuncSetAttribute(mma_gemm<3>, cudaFuncAttributeMaxDynamicSharedMemorySize, DYN_BYTES);

    // 0. round weights to tf32
    round_w_kernel<<<148, 256>>>(w_qkv, w_proj, w1, w2);

    // 1. LN1 + shift + window partition -> g_xw (tf32-rounded)
    ln_kernel<true><<<ROWS, 128>>>(x, g1, beta1, xw);

    // 2. QKV: [32768,1536] = xw @ wqkv^T
    mma_gemm<0><<<dim3(1536/BN, ROWS/BM), 256, DYN_BYTES>>>(xw, wq, b_qkv, nullptr, qkv, 1536, 512);

    // 3. attention -> g_ow (tf32-rounded)
    attn_mma<<<NWINDOWS, 256>>>(rpb);

    // 4. proj + window reverse + unshift + residual(x) -> g_x2
    mma_gemm<3><<<dim3(512/BN, ROWS/BM), 256, DYN_BYTES>>>(ow, wp, b_proj, x, x2, 512, 512);

    // 5. LN2 -> g_h2 (tf32-rounded)
    ln_kernel<false><<<ROWS, 128>>>(x2, g2, beta2, h2);

    // 6. FC1 + GELU -> g_m1 (tf32-rounded)
    mma_gemm<1><<<dim3(1024/BN, ROWS/BM), 256, DYN_BYTES>>>(h2, wa, b1, nullptr, m1, 1024, 512);

    // 7. FC2 + residual(g_x2) -> out
    mma_gemm<2><<<dim3(512/BN, ROWS/BM), 256, DYN_BYTES>>>(m1, wb, b2, x2, out, 512, 1024);
}

// round 7
// speedup vs baseline: 4.8407x; 1.1330x over previous
#include <cuda_runtime.h>
#include <cstdint>
#include <math.h>

// ---------------------------------------------------------------------------
// SwinTLayer: B=4, H=64, W=128, C=512, F=1024, NH=8, hd=64, WS=4, SS=2
// ---------------------------------------------------------------------------

#define BATCH   4
#define IMH     64
#define IMW     128
#define CDIM    512
#define LTOK    (IMH*IMW)            // 8192
#define NHEADS  8
#define HDIM    64
#define NWINDOWS 2048
#define ROWS    (NWINDOWS*16)         // 32768
#define FDIM    1024

// Scratch (device globals; cudaMalloc forbidden)
__device__ __align__(1024) float g_xw [ (size_t)ROWS*CDIM ];
__device__ __align__(1024) float g_qkv[ (size_t)ROWS*3*CDIM ];
__device__ __align__(1024) float g_ow [ (size_t)ROWS*CDIM ];
__device__ __align__(1024) float g_x2 [ (size_t)ROWS*CDIM ];
__device__ __align__(1024) float g_h2 [ (size_t)ROWS*CDIM ];
__device__ __align__(1024) float g_m1 [ (size_t)ROWS*FDIM ];
// tf32-rounded weight copies
__device__ __align__(1024) float g_wqkv[ 1536*512 ];
__device__ __align__(1024) float g_wproj[ 512*512 ];
__device__ __align__(1024) float g_w1  [ 1024*512 ];
__device__ __align__(1024) float g_w2  [ 512*1024 ];

// ---------------------------------------------------------------------------
// helpers
// ---------------------------------------------------------------------------
__device__ __forceinline__ float tf32r(float x) {
    uint32_t u;
    asm volatile("cvt.rna.tf32.f32 %0, %1;" : "=r"(u) : "f"(x));
    return __uint_as_float(u);
}
__device__ __forceinline__ uint32_t tf32u(float x) {
    uint32_t u;
    asm volatile("cvt.rna.tf32.f32 %0, %1;" : "=r"(u) : "f"(x));
    return u;
}

__device__ __forceinline__ uint32_t smem_u32(const void* p) {
    return (uint32_t)__cvta_generic_to_shared(p);
}

#define CP_ASYNC16(dst, src) \
    asm volatile("cp.async.cg.shared.global [%0], [%1], 16;" :: "r"(dst), "l"(src))
#define CP_COMMIT()  asm volatile("cp.async.commit_group;")
#define CP_WAIT1()   asm volatile("cp.async.wait_group 1;")

// m16n8k8 tf32 HMMA (legacy warp-level path; works on plain sm_103 target)
__device__ __forceinline__ void hmma_tf32(float* c,
                                          uint32_t a0, uint32_t a1, uint32_t a2, uint32_t a3,
                                          uint32_t b0, uint32_t b1)
{
    asm volatile(
        "mma.sync.aligned.m16n8k8.row.col.f32.tf32.tf32.f32 "
        "{%0,%1,%2,%3}, {%4,%5,%6,%7}, {%8,%9}, {%0,%1,%2,%3};"
        : "+f"(c[0]), "+f"(c[1]), "+f"(c[2]), "+f"(c[3])
        : "r"(a0), "r"(a1), "r"(a2), "r"(a3), "r"(b0), "r"(b1));
}

// ldmatrix x4 (b16 path reused for tf32: 8x4-float block = 8 rows x 16B,
// word w = row*4+col -> lane w, which is exactly the tf32 fragment layout)
__device__ __forceinline__ void ldsm4(uint32_t& r0, uint32_t& r1,
                                      uint32_t& r2, uint32_t& r3, uint32_t addr)
{
    asm volatile("ldmatrix.sync.aligned.m8n8.x4.shared.b16 {%0,%1,%2,%3}, [%4];"
                 : "=r"(r0), "=r"(r1), "=r"(r2), "=r"(r3) : "r"(addr));
}

// window-row -> token-row map (shift + window partition; same gather/scatter)
__device__ __forceinline__ int swin_token(int r)
{
    int win   = r >> 4;
    int n     = r & 15;
    int b     = win >> 9;
    int local = win & 511;
    int wi    = local >> 5;
    int wj    = local & 31;
    int h     = (wi * 4 + (n >> 2) + 2) & (IMH - 1);
    int w     = (wj * 4 + (n & 3) + 2) & (IMW - 1);
    return b * LTOK + h * IMW + w;
}

// ---------------------------------------------------------------------------
// weight rounding to tf32 (unbiased rna)
// ---------------------------------------------------------------------------
__global__ void round_w_kernel(const float* __restrict__ a, const float* __restrict__ b,
                               const float* __restrict__ c, const float* __restrict__ d)
{
    int i = blockIdx.x * blockDim.x + threadIdx.x;
    int stride = gridDim.x * blockDim.x;
    for (int t = i; t < 1536*512; t += stride) g_wqkv[t]  = tf32r(a[t]);
    for (int t = i; t < 512*512;  t += stride) g_wproj[t] = tf32r(b[t]);
    for (int t = i; t < 1024*512; t += stride) g_w1[t]    = tf32r(c[t]);
    for (int t = i; t < 512*1024; t += stride) g_w2[t]    = tf32r(d[t]);
}

// ---------------------------------------------------------------------------
// LayerNorm (C=512), 128 threads, float4/thread. GATHER: swin gather from x.
// Output rounded to tf32 (feeds MMA).
// ---------------------------------------------------------------------------
template <bool GATHER>
__global__ void ln_kernel(const float* __restrict__ src,
                          const float* __restrict__ gamma,
                          const float* __restrict__ beta,
                          float* __restrict__ dst)
{
    int r    = blockIdx.x;
    int srow = GATHER ? swin_token(r) : r;
    float4 v = ((const float4*)(src + (size_t)srow * CDIM))[threadIdx.x];

    float s  = v.x + v.y + v.z + v.w;
    float sq = v.x*v.x + v.y*v.y + v.z*v.z + v.w*v.w;
    #pragma unroll
    for (int o = 16; o; o >>= 1) {
        s  += __shfl_xor_sync(0xffffffffu, s,  o);
        sq += __shfl_xor_sync(0xffffffffu, sq, o);
    }
    __shared__ float ss[4], ssq[4];
    int warp = threadIdx.x >> 5;
    if ((threadIdx.x & 31) == 0) { ss[warp] = s; ssq[warp] = sq; }
    __syncthreads();
    s  = ss[0] + ss[1] + ss[2] + ss[3];
    sq = ssq[0] + ssq[1] + ssq[2] + ssq[3];

    float mean = s * (1.0f / CDIM);
    float var  = sq * (1.0f / CDIM) - mean * mean;
    float rstd = rsqrtf(var + 1e-5f);

    float4 gv = ((const float4*)gamma)[threadIdx.x];
    float4 bv = ((const float4*)beta)[threadIdx.x];
    float4 o;
    o.x = tf32r((v.x - mean) * rstd * gv.x + bv.x);
    o.y = tf32r((v.y - mean) * rstd * gv.y + bv.y);
    o.z = tf32r((v.z - mean) * rstd * gv.z + bv.z);
    o.w = tf32r((v.w - mean) * rstd * gv.w + bv.w);
    ((float4*)(dst + (size_t)r * CDIM))[threadIdx.x] = o;
}

// ---------------------------------------------------------------------------
// HMMA tf32 GEMM: C[M,N] = A[M,K] @ B[N,K]^T (+bias, epilogue).
// CTA tile 128x128, BK=32, 128 threads (4 warps, each 64x64),
// 3-stage cp.async pipeline (96KB -> 2 CTAs/SM), XOR-swizzled SMEM,
// all fragment loads via ldmatrix.x4.
// EPI: 0 bias | 1 bias+GELU+tf32round | 2 bias+aux[r,c] | 3 bias+swin scatter+aux
// ---------------------------------------------------------------------------
#define BM 128
#define BN 128
#define BK 32
#define NSTAGES 3
#define STAGE_FLOATS ((BM + BN) * BK)           // 8192 floats = 32KB
#define STAGE_BYTES  (STAGE_FLOATS * 4)
#define DYN_BYTES    (NSTAGES * STAGE_BYTES)    // 98304

template <int EPI>
__global__ void __launch_bounds__(128, 2)
mma_gemm(const float* __restrict__ A, const float* __restrict__ Bm,
         const float* __restrict__ bias, const float* __restrict__ aux,
         float* __restrict__ C, int Nn, int K)
{
    extern __shared__ char dyn[];
    uint32_t smem_base = smem_u32(dyn);

    int tid  = threadIdx.x;
    int wid  = tid >> 5;
    int lane = tid & 31;
    int rA   = lane >> 2;       // 0..7 (acc layout)
    int cA   = lane & 3;        // 0..3

    int m0 = (wid & 1) * 64;    // 2 warp rows (64 each)
    int n0 = (wid >> 1) * 64;   // 2 warp cols (64 each)

    int row0 = blockIdx.y * BM;
    int col0 = blockIdx.x * BN;
    int S    = K >> 5;          // K-slices of 32 floats

    const float* Abase = A  + (size_t)row0 * K;
    const float* Bbase = Bm + (size_t)col0 * K;

    // ldmatrix per-lane address components
    uint32_t lxor   = (uint32_t)(lane & 7);
    uint32_t arow   = (uint32_t)(m0 + (lane & 15));           // A rows for grp 0/1
    uint32_t ac0    = (uint32_t)(lane >> 4);                  // chunk offset (0/1)
    uint32_t brow   = (uint32_t)(n0 + ((lane >> 4) << 3) + (lane & 7));
    uint32_t bc0    = (uint32_t)((lane >> 3) & 1);

    // ---- async tile loader: 16 cp.async (16B) per thread per stage ----
    auto load_slice = [&](int ks, int st) {
        uint32_t sA = smem_base + st * STAGE_BYTES;
        uint32_t sB = sA + BM * BK * 4;
        const float* Ap = Abase + ks * BK;
        const float* Bp = Bbase + ks * BK;
        #pragma unroll
        for (int p = 0; p < 8; p++) {                  // A: 1024 chunks
            int idx = p * 128 + tid;
            int row = idx >> 3, ch = idx & 7;
            CP_ASYNC16(sA + (uint32_t)(row * 128 + ((ch ^ (row & 7)) * 16)),
                       Ap + (size_t)row * K + ch * 4);
        }
        #pragma unroll
        for (int p = 0; p < 8; p++) {                  // B: 1024 chunks
            int idx = p * 128 + tid;
            int row = idx >> 3, ch = idx & 7;
            CP_ASYNC16(sB + (uint32_t)(row * 128 + ((ch ^ (row & 7)) * 16)),
                       Bp + (size_t)row * K + ch * 4);
        }
    };

    float acc[4][8][4];
    #pragma unroll
    for (int i = 0; i < 4; i++)
        #pragma unroll
        for (int j = 0; j < 8; j++)
            #pragma unroll
            for (int q = 0; q < 4; q++) acc[i][j][q] = 0.0f;

    load_slice(0, 0); CP_COMMIT();
    load_slice(1, 1); CP_COMMIT();

    for (int ks = 0; ks < S; ks++) {
        int st = ks % NSTAGES;
        CP_WAIT1();
        __syncthreads();

        // issue next tile's loads before compute (requests overlap MMA burst)
        if (ks + 2 < S) load_slice(ks + 2, (ks + 2) % NSTAGES);
        CP_COMMIT();

        uint32_t sA = smem_base + st * STAGE_BYTES;
        uint32_t sB = sA + BM * BK * 4;

        #pragma unroll
        for (int kt = 0; kt < 4; kt++) {
            // A fragments: 4 m-tiles of 16 rows, via ldmatrix.x4
            uint32_t af[4][4];
            #pragma unroll
            for (int mt = 0; mt < 4; mt++) {
                uint32_t row = arow + mt * 16;
                uint32_t ch  = (uint32_t)(kt * 2) + ac0;
                ldsm4(af[mt][0], af[mt][1], af[mt][2], af[mt][3],
                      sA + row * 128 + ((ch ^ lxor) * 16));
            }
            // B fragments: 8 n-tiles of 8 cols, pairs via ldmatrix.x4
            uint32_t bf[8][2];
            #pragma unroll
            for (int ntp = 0; ntp < 4; ntp++) {
                uint32_t row = brow + ntp * 16;
                uint32_t ch  = (uint32_t)(kt * 2) + bc0;
                ldsm4(bf[2*ntp][0], bf[2*ntp][1], bf[2*ntp+1][0], bf[2*ntp+1][1],
                      sB + row * 128 + ((ch ^ lxor) * 16));
            }
            #pragma unroll
            for (int mt = 0; mt < 4; mt++)
                #pragma unroll
                for (int nt = 0; nt < 8; nt++)
                    hmma_tf32(acc[mt][nt], af[mt][0], af[mt][1], af[mt][2], af[mt][3],
                              bf[nt][0], bf[nt][1]);
        }
    }

    // ---- epilogue: direct float2 stores ----
    #pragma unroll
    for (int mt = 0; mt < 4; mt++) {
        #pragma unroll
        for (int half = 0; half < 2; half++) {
            int grow = row0 + m0 + mt * 16 + half * 8 + rA;
            int tt   = (EPI == 3) ? swin_token(grow) : grow;
            #pragma unroll
            for (int nt = 0; nt < 8; nt++) {
                int col = col0 + n0 + nt * 8 + cA * 2;
                float v0 = acc[mt][nt][half * 2 + 0] + bias[col];
                float v1 = acc[mt][nt][half * 2 + 1] + bias[col + 1];
                if (EPI == 1) {
                    v0 = tf32r(0.5f * v0 * (1.0f + erff(v0 * 0.70710678118654752f)));
                    v1 = tf32r(0.5f * v1 * (1.0f + erff(v1 * 0.70710678118654752f)));
                } else if (EPI == 2) {
                    float2 ax = *(const float2*)(aux + (size_t)grow * Nn + col);
                    v0 += ax.x; v1 += ax.y;
                } else if (EPI == 3) {
                    float2 ax = *(const float2*)(aux + (size_t)tt * CDIM + col);
                    v0 += ax.x; v1 += ax.y;
                }
                float2 o = make_float2(v0, v1);
                if (EPI == 3) *(float2*)(C + (size_t)tt * CDIM + col) = o;
                else          *(float2*)(C + (size_t)grow * Nn + col) = o;
            }
        }
    }
}

// ---------------------------------------------------------------------------
// Windowed attention via HMMA: one warp per (window, head).
// Block = 256 threads = 8 warps = 8 heads of one window. Grid = 2048.
// ---------------------------------------------------------------------------
__global__ void __launch_bounds__(256) attn_mma(const float* __restrict__ rpb)
{
    __shared__ __align__(16) float sp[8][16][18];   // P tiles, padded rows (72B)

    int win  = blockIdx.x;
    int head = threadIdx.x >> 5;
    int lane = threadIdx.x & 31;
    int rhi  = lane >> 2;       // 0..7
    int rlo  = lane & 3;        // 0..3

    const float* qb = g_qkv + (size_t)(win * 16) * 1536 + head * 64;
    const float* kb = qb + 512;
    const float* vb = qb + 1024;

    int local = win & 511;
    int wi = local >> 5, wj = local & 31;

    auto reg_of = [&](int tok) {
        int hs = wi * 4 + (tok >> 2);
        int ws = wj * 4 + (tok & 3);
        int rh = hs < (IMH - 4) ? 0 : (hs < (IMH - 2) ? 1 : 2);
        int rw = ws < (IMW - 4) ? 0 : (ws < (IMW - 2) ? 1 : 2);
        return rh * 3 + rw;
    };

    // ---- S = (Q*scale) K^T : two 16x8 n-tiles ----
    float s0[4] = {0,0,0,0}, s1[4] = {0,0,0,0};
    #pragma unroll
    for (int kt = 0; kt < 8; kt++) {
        int c = kt * 8 + rlo;
        uint32_t a0 = tf32u(qb[(size_t)rhi * 1536 + c] * 0.125f);
        uint32_t a1 = tf32u(qb[(size_t)(rhi + 8) * 1536 + c] * 0.125f);
        uint32_t a2 = tf32u(qb[(size_t)rhi * 1536 + c + 4] * 0.125f);
        uint32_t a3 = tf32u(qb[(size_t)(rhi + 8) * 1536 + c + 4] * 0.125f);
        uint32_t b0 = tf32u(kb[(size_t)rhi * 1536 + c]);
        uint32_t b1 = tf32u(kb[(size_t)rhi * 1536 + c + 4]);
        hmma_tf32(s0, a0, a1, a2, a3, b0, b1);
        b0 = tf32u(kb[(size_t)(rhi + 8) * 1536 + c]);
        b1 = tf32u(kb[(size_t)(rhi + 8) * 1536 + c + 4]);
        hmma_tf32(s1, a0, a1, a2, a3, b0, b1);
    }

    // ---- + rel-pos bias + shift mask ----
    int i0 = rhi, i1 = rhi + 8;
    int ri0 = reg_of(i0), ri1 = reg_of(i1);
    #pragma unroll
    for (int nt = 0; nt < 2; nt++) {
        float* s = nt ? s1 : s0;
        #pragma unroll
        for (int q = 0; q < 4; q++) {
            int i  = (q < 2) ? i0 : i1;
            int ri = (q < 2) ? ri0 : ri1;
            int j  = nt * 8 + 2 * rlo + (q & 1);
            int idx = ((i >> 2) - (j >> 2) + 3) * 7 + ((i & 3) - (j & 3) + 3);
            float b = __ldg(rpb + idx * NHEADS + head);
            s[q] += b + ((ri != reg_of(j)) ? -100.0f : 0.0f);
        }
    }

    // ---- softmax ----
    float m0 = fmaxf(fmaxf(s0[0], s0[1]), fmaxf(s1[0], s1[1]));
    float m1 = fmaxf(fmaxf(s0[2], s0[3]), fmaxf(s1[2], s1[3]));
    m0 = fmaxf(m0, __shfl_xor_sync(~0u, m0, 1));
    m0 = fmaxf(m0, __shfl_xor_sync(~0u, m0, 2));
    m1 = fmaxf(m1, __shfl_xor_sync(~0u, m1, 1));
    m1 = fmaxf(m1, __shfl_xor_sync(~0u, m1, 2));
    s0[0] = __expf(s0[0] - m0); s0[1] = __expf(s0[1] - m0);
    s1[0] = __expf(s1[0] - m0); s1[1] = __expf(s1[1] - m0);
    s0[2] = __expf(s0[2] - m1); s0[3] = __expf(s0[3] - m1);
    s1[2] = __expf(s1[2] - m1); s1[3] = __expf(s1[3] - m1);
    float t0 = s0[0] + s0[1] + s1[0] + s1[1];
    float t1 = s0[2] + s0[3] + s1[2] + s1[3];
    t0 += __shfl_xor_sync(~0u, t0, 1); t0 += __shfl_xor_sync(~0u, t0, 2);
    t1 += __shfl_xor_sync(~0u, t1, 1); t1 += __shfl_xor_sync(~0u, t1, 2);
    float inv0 = 1.0f / t0, inv1 = 1.0f / t1;

    // ---- P -> smem -> A-fragment layout ----
    #pragma unroll
    for (int nt = 0; nt < 2; nt++) {
        const float* s = nt ? s1 : s0;
        *(float2*)&sp[head][i0][nt * 8 + 2 * rlo] =
            make_float2(tf32r(s[0] * inv0), tf32r(s[1] * inv0));
        *(float2*)&sp[head][i1][nt * 8 + 2 * rlo] =
            make_float2(tf32r(s[2] * inv1), tf32r(s[3] * inv1));
    }
    __syncwarp();

    uint32_t pa[2][4];
    #pragma unroll
    for (int kt = 0; kt < 2; kt++) {
        pa[kt][0] = __float_as_uint(sp[head][i0][kt * 8 + rlo]);
        pa[kt][1] = __float_as_uint(sp[head][i1][kt * 8 + rlo]);
        pa[kt][2] = __float_as_uint(sp[head][i0][kt * 8 + rlo + 4]);
        pa[kt][3] = __float_as_uint(sp[head][i1][kt * 8 + rlo + 4]);
    }

    // ---- O = P V ----
    float* ob = g_ow + (size_t)(win * 16) * CDIM + head * 64;
    #pragma unroll
    for (int nt = 0; nt < 8; nt++) {
        float o[4] = {0, 0, 0, 0};
        #pragma unroll
        for (int kt = 0; kt < 2; kt++) {
            uint32_t b0 = tf32u(vb[(size_t)(kt * 8 + rlo) * 1536 + nt * 8 + rhi]);
            uint32_t b1 = tf32u(vb[(size_t)(kt * 8 + rlo + 4) * 1536 + nt * 8 + rhi]);
            hmma_tf32(o, pa[kt][0], pa[kt][1], pa[kt][2], pa[kt][3], b0, b1);
        }
        int col = nt * 8 + 2 * rlo;
        *(float2*)&ob[(size_t)i0 * CDIM + col] = make_float2(tf32r(o[0]), tf32r(o[1]));
        *(float2*)&ob[(size_t)i1 * CDIM + col] = make_float2(tf32r(o[2]), tf32r(o[3]));
    }
}

// ---------------------------------------------------------------------------
// Launch
// ---------------------------------------------------------------------------
extern "C" void kernel_launch(void* const* d_in, const int* in_sizes, int n_in,
                              void* d_out, int out_size)
{
    const float* x      = (const float*)d_in[0];
    const float* g1     = (const float*)d_in[1];
    const float* beta1  = (const float*)d_in[2];
    const float* w_qkv  = (const float*)d_in[3];
    const float* b_qkv  = (const float*)d_in[4];
    const float* rpb    = (const float*)d_in[5];
    const float* w_proj = (const float*)d_in[6];
    const float* b_proj = (const float*)d_in[7];
    const float* g2     = (const float*)d_in[8];
    const float* beta2  = (const float*)d_in[9];
    const float* w1     = (const float*)d_in[10];
    const float* b1     = (const float*)d_in[11];
    const float* w2     = (const float*)d_in[12];
    const float* b2     = (const float*)d_in[13];
    float* out = (float*)d_out;

    float *xw, *ow, *x2, *h2, *m1, *qkv;
    float *wq, *wp, *wa, *wb;
    cudaGetSymbolAddress((void**)&xw,  g_xw);
    cudaGetSymbolAddress((void**)&qkv, g_qkv);
    cudaGetSymbolAddress((void**)&ow,  g_ow);
    cudaGetSymbolAddress((void**)&x2,  g_x2);
    cudaGetSymbolAddress((void**)&h2,  g_h2);
    cudaGetSymbolAddress((void**)&m1,  g_m1);
    cudaGetSymbolAddress((void**)&wq,  g_wqkv);
    cudaGetSymbolAddress((void**)&wp,  g_wproj);
    cudaGetSymbolAddress((void**)&wa,  g_w1);
    cudaGetSymbolAddress((void**)&wb,  g_w2);

    cudaFuncSetAttribute(mma_gemm<0>, cudaFuncAttributeMaxDynamicSharedMemorySize, DYN_BYTES);
    cudaFuncSetAttribute(mma_gemm<1>, cudaFuncAttributeMaxDynamicSharedMemorySize, DYN_BYTES);
    cudaFuncSetAttribute(mma_gemm<2>, cudaFuncAttributeMaxDynamicSharedMemorySize, DYN_BYTES);
    cudaFuncSetAttribute(mma_gemm<3>, cudaFuncAttributeMaxDynamicSharedMemorySize, DYN_BYTES);

    // 0. round weights to tf32
    round_w_kernel<<<148, 256>>>(w_qkv, w_proj, w1, w2);

    // 1. LN1 + shift + window partition -> g_xw (tf32-rounded)
    ln_kernel<true><<<ROWS, 128>>>(x, g1, beta1, xw);

    // 2. QKV: [32768,1536] = xw @ wqkv^T
    mma_gemm<0><<<dim3(1536/BN, ROWS/BM), 128, DYN_BYTES>>>(xw, wq, b_qkv, nullptr, qkv, 1536, 512);

    // 3. attention -> g_ow (tf32-rounded)
    attn_mma<<<NWINDOWS, 256>>>(rpb);

    // 4. proj + window reverse + unshift + residual(x) -> g_x2
    mma_gemm<3><<<dim3(512/BN, ROWS/BM), 128, DYN_BYTES>>>(ow, wp, b_proj, x, x2, 512, 512);

    // 5. LN2 -> g_h2 (tf32-rounded)
    ln_kernel<false><<<ROWS, 128>>>(x2, g2, beta2, h2);

    // 6. FC1 + GELU -> g_m1 (tf32-rounded)
    mma_gemm<1><<<dim3(1024/BN, ROWS/BM), 128, DYN_BYTES>>>(h2, wa, b1, nullptr, m1, 1024, 512);

    // 7. FC2 + residual(g_x2) -> out
    mma_gemm<2><<<dim3(512/BN, ROWS/BM), 128, DYN_BYTES>>>(m1, wb, b2, x2, out, 512, 1024);
}

// round 8
// speedup vs baseline: 7.9615x; 1.6447x over previous
#include <cuda_runtime.h>
#include <cuda_bf16.h>
#include <cstdint>
#include <math.h>

// ---------------------------------------------------------------------------
// SwinTLayer: B=4, H=64, W=128, C=512, F=1024, NH=8, hd=64, WS=4, SS=2
// bf16 HMMA (m16n8k16) everywhere; fp32 accum, fp32 LN/softmax/GELU/residual.
// ---------------------------------------------------------------------------

#define BATCH   4
#define IMH     64
#define IMW     128
#define CDIM    512
#define LTOK    (IMH*IMW)            // 8192
#define NHEADS  8
#define HDIM    64
#define NWINDOWS 2048
#define ROWS    (NWINDOWS*16)         // 32768
#define FDIM    1024

typedef __nv_bfloat16 bf16;

// Scratch (device globals; cudaMalloc forbidden)
__device__ __align__(1024) bf16  g_xw [ (size_t)ROWS*CDIM ];
__device__ __align__(1024) bf16  g_qkv[ (size_t)ROWS*3*CDIM ];
__device__ __align__(1024) bf16  g_ow [ (size_t)ROWS*CDIM ];
__device__ __align__(1024) float g_x2 [ (size_t)ROWS*CDIM ];   // residual, fp32
__device__ __align__(1024) bf16  g_h2 [ (size_t)ROWS*CDIM ];
__device__ __align__(1024) bf16  g_m1 [ (size_t)ROWS*FDIM ];
// bf16 weight copies
__device__ __align__(1024) bf16 g_wqkv[ 1536*512 ];
__device__ __align__(1024) bf16 g_wproj[ 512*512 ];
__device__ __align__(1024) bf16 g_w1  [ 1024*512 ];
__device__ __align__(1024) bf16 g_w2  [ 512*1024 ];

// ---------------------------------------------------------------------------
// helpers
// ---------------------------------------------------------------------------
__device__ __forceinline__ uint32_t smem_u32(const void* p) {
    return (uint32_t)__cvta_generic_to_shared(p);
}

__device__ __forceinline__ uint32_t bf2(float lo, float hi) {
    __nv_bfloat162 t = __floats2bfloat162_rn(lo, hi);
    return *reinterpret_cast<uint32_t*>(&t);
}
__device__ __forceinline__ uint32_t packh(bf16 lo, bf16 hi) {
    __nv_bfloat162 t(lo, hi);
    return *reinterpret_cast<uint32_t*>(&t);
}

#define CP_ASYNC16(dst, src) \
    asm volatile("cp.async.cg.shared.global [%0], [%1], 16;" :: "r"(dst), "l"(src))
#define CP_COMMIT()  asm volatile("cp.async.commit_group;")
#define CP_WAIT1()   asm volatile("cp.async.wait_group 1;")

// m16n8k16 bf16 HMMA (legacy warp path; valid on plain sm_103 target)
__device__ __forceinline__ void hmma_bf16(float* c,
                                          uint32_t a0, uint32_t a1, uint32_t a2, uint32_t a3,
                                          uint32_t b0, uint32_t b1)
{
    asm volatile(
        "mma.sync.aligned.m16n8k16.row.col.f32.bf16.bf16.f32 "
        "{%0,%1,%2,%3}, {%4,%5,%6,%7}, {%8,%9}, {%0,%1,%2,%3};"
        : "+f"(c[0]), "+f"(c[1]), "+f"(c[2]), "+f"(c[3])
        : "r"(a0), "r"(a1), "r"(a2), "r"(a3), "r"(b0), "r"(b1));
}

__device__ __forceinline__ void ldsm4(uint32_t& r0, uint32_t& r1,
                                      uint32_t& r2, uint32_t& r3, uint32_t addr)
{
    asm volatile("ldmatrix.sync.aligned.m8n8.x4.shared.b16 {%0,%1,%2,%3}, [%4];"
                 : "=r"(r0), "=r"(r1), "=r"(r2), "=r"(r3) : "r"(addr));
}

// window-row -> token-row map (shift + window partition; same gather/scatter)
__device__ __forceinline__ int swin_token(int r)
{
    int win   = r >> 4;
    int n     = r & 15;
    int b     = win >> 9;
    int local = win & 511;
    int wi    = local >> 5;
    int wj    = local & 31;
    int h     = (wi * 4 + (n >> 2) + 2) & (IMH - 1);
    int w     = (wj * 4 + (n & 3) + 2) & (IMW - 1);
    return b * LTOK + h * IMW + w;
}

// ---------------------------------------------------------------------------
// weight rounding to bf16 (rne)
// ---------------------------------------------------------------------------
__global__ void round_w_kernel(const float* __restrict__ a, const float* __restrict__ b,
                               const float* __restrict__ c, const float* __restrict__ d)
{
    int i = blockIdx.x * blockDim.x + threadIdx.x;
    int stride = gridDim.x * blockDim.x;
    for (int t = i; t < 1536*512; t += stride) g_wqkv[t]  = __float2bfloat16_rn(a[t]);
    for (int t = i; t < 512*512;  t += stride) g_wproj[t] = __float2bfloat16_rn(b[t]);
    for (int t = i; t < 1024*512; t += stride) g_w1[t]    = __float2bfloat16_rn(c[t]);
    for (int t = i; t < 512*1024; t += stride) g_w2[t]    = __float2bfloat16_rn(d[t]);
}

// ---------------------------------------------------------------------------
// LayerNorm (C=512), 128 threads, float4/thread, bf16 output.
// GATHER: swin gather from x (LN1 + shift + window partition).
// ---------------------------------------------------------------------------
template <bool GATHER>
__global__ void ln_kernel(const float* __restrict__ src,
                          const float* __restrict__ gamma,
                          const float* __restrict__ beta,
                          bf16* __restrict__ dst)
{
    int r    = blockIdx.x;
    int srow = GATHER ? swin_token(r) : r;
    float4 v = ((const float4*)(src + (size_t)srow * CDIM))[threadIdx.x];

    float s  = v.x + v.y + v.z + v.w;
    float sq = v.x*v.x + v.y*v.y + v.z*v.z + v.w*v.w;
    #pragma unroll
    for (int o = 16; o; o >>= 1) {
        s  += __shfl_xor_sync(0xffffffffu, s,  o);
        sq += __shfl_xor_sync(0xffffffffu, sq, o);
    }
    __shared__ float ss[4], ssq[4];
    int warp = threadIdx.x >> 5;
    if ((threadIdx.x & 31) == 0) { ss[warp] = s; ssq[warp] = sq; }
    __syncthreads();
    s  = ss[0] + ss[1] + ss[2] + ss[3];
    sq = ssq[0] + ssq[1] + ssq[2] + ssq[3];

    float mean = s * (1.0f / CDIM);
    float var  = sq * (1.0f / CDIM) - mean * mean;
    float rstd = rsqrtf(var + 1e-5f);

    float4 gv = ((const float4*)gamma)[threadIdx.x];
    float4 bv = ((const float4*)beta)[threadIdx.x];
    uint2 o;
    o.x = bf2((v.x - mean) * rstd * gv.x + bv.x, (v.y - mean) * rstd * gv.y + bv.y);
    o.y = bf2((v.z - mean) * rstd * gv.z + bv.z, (v.w - mean) * rstd * gv.w + bv.w);
    ((uint2*)(dst + (size_t)r * CDIM))[threadIdx.x] = o;
}

// ---------------------------------------------------------------------------
// bf16 HMMA GEMM: C[M,N] = A[M,K] @ B[N,K]^T (+bias, epilogue).
// CTA 128x128, BK=64 bf16 (128B/row), 128 threads (4 warps, 64x64 each),
// 3-stage cp.async (96KB -> 2 CTAs/SM), XOR swizzle, ldmatrix.x4 fragments.
// EPI: 0 bias->bf16 | 1 bias+GELU->bf16 | 2 bias+aux->fp32 | 3 bias+swin scatter+aux->fp32
// ---------------------------------------------------------------------------
#define BM 128
#define BN 128
#define BKE 64                                   // K elements per slice
#define NSTAGES 3
#define STAGE_BYTES ((BM + BN) * BKE * 2)        // 32768
#define DYN_BYTES   (NSTAGES * STAGE_BYTES)      // 98304

template <int EPI>
__global__ void __launch_bounds__(128, 2)
mma_gemm(const bf16* __restrict__ A, const bf16* __restrict__ Bm,
         const float* __restrict__ bias, const float* __restrict__ aux,
         void* __restrict__ Cv, int Nn, int K)
{
    extern __shared__ char dyn[];
    uint32_t smem_base = smem_u32(dyn);

    int tid  = threadIdx.x;
    int wid  = tid >> 5;
    int lane = tid & 31;
    int rA   = lane >> 2;       // 0..7 (acc layout)
    int cA   = lane & 3;        // 0..3

    int m0 = (wid & 1) * 64;
    int n0 = (wid >> 1) * 64;

    int row0 = blockIdx.y * BM;
    int col0 = blockIdx.x * BN;
    int S    = K >> 6;          // K-slices of 64 bf16

    const bf16* Abase = A  + (size_t)row0 * K;
    const bf16* Bbase = Bm + (size_t)col0 * K;

    uint32_t lxor = (uint32_t)(lane & 7);
    uint32_t arow = (uint32_t)(m0 + (lane & 15));
    uint32_t ac0  = (uint32_t)(lane >> 4);
    uint32_t brow = (uint32_t)(n0 + ((lane >> 4) << 3) + (lane & 7));
    uint32_t bc0  = (uint32_t)((lane >> 3) & 1);

    // ---- async tile loader: 16 cp.async (16B = 8 bf16) per thread/stage ----
    auto load_slice = [&](int ks, int st) {
        uint32_t sA = smem_base + st * STAGE_BYTES;
        uint32_t sB = sA + BM * 128;
        const bf16* Ap = Abase + ks * BKE;
        const bf16* Bp = Bbase + ks * BKE;
        #pragma unroll
        for (int p = 0; p < 8; p++) {                  // A: 1024 chunks
            int idx = p * 128 + tid;
            int row = idx >> 3, ch = idx & 7;
            CP_ASYNC16(sA + (uint32_t)(row * 128 + ((ch ^ (row & 7)) * 16)),
                       Ap + (size_t)row * K + ch * 8);
        }
        #pragma unroll
        for (int p = 0; p < 8; p++) {                  // B: 1024 chunks
            int idx = p * 128 + tid;
            int row = idx >> 3, ch = idx & 7;
            CP_ASYNC16(sB + (uint32_t)(row * 128 + ((ch ^ (row & 7)) * 16)),
                       Bp + (size_t)row * K + ch * 8);
        }
    };

    float acc[4][8][4];
    #pragma unroll
    for (int i = 0; i < 4; i++)
        #pragma unroll
        for (int j = 0; j < 8; j++)
            #pragma unroll
            for (int q = 0; q < 4; q++) acc[i][j][q] = 0.0f;

    load_slice(0, 0); CP_COMMIT();
    load_slice(1, 1); CP_COMMIT();

    for (int ks = 0; ks < S; ks++) {
        int st = ks % NSTAGES;
        CP_WAIT1();
        __syncthreads();

        if (ks + 2 < S) load_slice(ks + 2, (ks + 2) % NSTAGES);
        CP_COMMIT();

        uint32_t sA = smem_base + st * STAGE_BYTES;
        uint32_t sB = sA + BM * 128;

        #pragma unroll
        for (int kt = 0; kt < 4; kt++) {               // 4 x k16 per slice
            uint32_t af[4][4];
            #pragma unroll
            for (int mt = 0; mt < 4; mt++) {
                uint32_t row = arow + mt * 16;
                uint32_t ch  = (uint32_t)(kt * 2) + ac0;
                ldsm4(af[mt][0], af[mt][1], af[mt][2], af[mt][3],
                      sA + row * 128 + ((ch ^ lxor) * 16));
            }
            uint32_t bf[8][2];
            #pragma unroll
            for (int ntp = 0; ntp < 4; ntp++) {
                uint32_t row = brow + ntp * 16;
                uint32_t ch  = (uint32_t)(kt * 2) + bc0;
                ldsm4(bf[2*ntp][0], bf[2*ntp][1], bf[2*ntp+1][0], bf[2*ntp+1][1],
                      sB + row * 128 + ((ch ^ lxor) * 16));
            }
            #pragma unroll
            for (int mt = 0; mt < 4; mt++)
                #pragma unroll
                for (int nt = 0; nt < 8; nt++)
                    hmma_bf16(acc[mt][nt], af[mt][0], af[mt][1], af[mt][2], af[mt][3],
                              bf[nt][0], bf[nt][1]);
        }
    }

    // ---- epilogue ----
    #pragma unroll
    for (int mt = 0; mt < 4; mt++) {
        #pragma unroll
        for (int half = 0; half < 2; half++) {
            int grow = row0 + m0 + mt * 16 + half * 8 + rA;
            int tt   = (EPI == 3) ? swin_token(grow) : grow;
            #pragma unroll
            for (int nt = 0; nt < 8; nt++) {
                int col = col0 + n0 + nt * 8 + cA * 2;
                float v0 = acc[mt][nt][half * 2 + 0] + bias[col];
                float v1 = acc[mt][nt][half * 2 + 1] + bias[col + 1];
                if (EPI == 0) {
                    *(uint32_t*)((bf16*)Cv + (size_t)grow * Nn + col) = bf2(v0, v1);
                } else if (EPI == 1) {
                    v0 = 0.5f * v0 * (1.0f + erff(v0 * 0.70710678118654752f));
                    v1 = 0.5f * v1 * (1.0f + erff(v1 * 0.70710678118654752f));
                    *(uint32_t*)((bf16*)Cv + (size_t)grow * Nn + col) = bf2(v0, v1);
                } else if (EPI == 2) {
                    float2 ax = *(const float2*)(aux + (size_t)grow * Nn + col);
                    *(float2*)((float*)Cv + (size_t)grow * Nn + col) =
                        make_float2(v0 + ax.x, v1 + ax.y);
                } else {
                    float2 ax = *(const float2*)(aux + (size_t)tt * CDIM + col);
                    *(float2*)((float*)Cv + (size_t)tt * CDIM + col) =
                        make_float2(v0 + ax.x, v1 + ax.y);
                }
            }
        }
    }
}

// ---------------------------------------------------------------------------
// Windowed attention via bf16 HMMA: one warp per (window, head).
// Block = 256 threads = 8 warps = 8 heads of one window. Grid = 2048.
// S-accumulator pairs ARE the P A-fragment layout in bf16-k16 -> no smem.
// ---------------------------------------------------------------------------
__global__ void __launch_bounds__(256) attn_mma(const float* __restrict__ rpb)
{
    int win  = blockIdx.x;
    int head = threadIdx.x >> 5;
    int lane = threadIdx.x & 31;
    int rhi  = lane >> 2;       // 0..7
    int rlo  = lane & 3;        // 0..3

    const bf16* qb = g_qkv + (size_t)(win * 16) * 1536 + head * 64;
    const bf16* kb = qb + 512;
    const bf16* vb = qb + 1024;

    int local = win & 511;
    int wi = local >> 5, wj = local & 31;

    auto reg_of = [&](int tok) {
        int hs = wi * 4 + (tok >> 2);
        int ws = wj * 4 + (tok & 3);
        int rh = hs < (IMH - 4) ? 0 : (hs < (IMH - 2) ? 1 : 2);
        int rw = ws < (IMW - 4) ? 0 : (ws < (IMW - 2) ? 1 : 2);
        return rh * 3 + rw;
    };

    int i0 = rhi, i1 = rhi + 8;
    const __nv_bfloat162 scl = __float2bfloat162_rn(0.125f);   // exact

    auto ldq = [&](const bf16* p) {
        __nv_bfloat162 t = __hmul2(*(const __nv_bfloat162*)p, scl);
        return *reinterpret_cast<uint32_t*>(&t);
    };

    // ---- S = (Q*scale) K^T : m16n8k16, 4 k-steps, 2 n-tiles ----
    float s0[4] = {0,0,0,0}, s1[4] = {0,0,0,0};
    #pragma unroll
    for (int kt = 0; kt < 4; kt++) {
        int c = kt * 16 + 2 * rlo;
        uint32_t a0 = ldq(qb + (size_t)i0 * 1536 + c);
        uint32_t a1 = ldq(qb + (size_t)i1 * 1536 + c);
        uint32_t a2 = ldq(qb + (size_t)i0 * 1536 + c + 8);
        uint32_t a3 = ldq(qb + (size_t)i1 * 1536 + c + 8);
        uint32_t b0 = *(const uint32_t*)(kb + (size_t)rhi * 1536 + c);
        uint32_t b1 = *(const uint32_t*)(kb + (size_t)rhi * 1536 + c + 8);
        hmma_bf16(s0, a0, a1, a2, a3, b0, b1);
        b0 = *(const uint32_t*)(kb + (size_t)(rhi + 8) * 1536 + c);
        b1 = *(const uint32_t*)(kb + (size_t)(rhi + 8) * 1536 + c + 8);
        hmma_bf16(s1, a0, a1, a2, a3, b0, b1);
    }

    // ---- + rel-pos bias + shift mask ----
    int ri0 = reg_of(i0), ri1 = reg_of(i1);
    #pragma unroll
    for (int nt = 0; nt < 2; nt++) {
        float* s = nt ? s1 : s0;
        #pragma unroll
        for (int q = 0; q < 4; q++) {
            int i  = (q < 2) ? i0 : i1;
            int ri = (q < 2) ? ri0 : ri1;
            int j  = nt * 8 + 2 * rlo + (q & 1);
            int idx = ((i >> 2) - (j >> 2) + 3) * 7 + ((i & 3) - (j & 3) + 3);
            float b = __ldg(rpb + idx * NHEADS + head);
            s[q] += b + ((ri != reg_of(j)) ? -100.0f : 0.0f);
        }
    }

    // ---- softmax (rows i0: regs 0,1 ; i1: regs 2,3 ; quad reduce) ----
    float m0 = fmaxf(fmaxf(s0[0], s0[1]), fmaxf(s1[0], s1[1]));
    float m1 = fmaxf(fmaxf(s0[2], s0[3]), fmaxf(s1[2], s1[3]));
    m0 = fmaxf(m0, __shfl_xor_sync(~0u, m0, 1));
    m0 = fmaxf(m0, __shfl_xor_sync(~0u, m0, 2));
    m1 = fmaxf(m1, __shfl_xor_sync(~0u, m1, 1));
    m1 = fmaxf(m1, __shfl_xor_sync(~0u, m1, 2));
    s0[0] = __expf(s0[0] - m0); s0[1] = __expf(s0[1] - m0);
    s1[0] = __expf(s1[0] - m0); s1[1] = __expf(s1[1] - m0);
    s0[2] = __expf(s0[2] - m1); s0[3] = __expf(s0[3] - m1);
    s1[2] = __expf(s1[2] - m1); s1[3] = __expf(s1[3] - m1);
    float t0 = s0[0] + s0[1] + s1[0] + s1[1];
    float t1 = s0[2] + s0[3] + s1[2] + s1[3];
    t0 += __shfl_xor_sync(~0u, t0, 1); t0 += __shfl_xor_sync(~0u, t0, 2);
    t1 += __shfl_xor_sync(~0u, t1, 1); t1 += __shfl_xor_sync(~0u, t1, 2);
    float inv0 = 1.0f / t0, inv1 = 1.0f / t1;

    // ---- P in A-fragment layout directly (acc pairs == a-frag pairs) ----
    uint32_t pa0 = bf2(s0[0] * inv0, s0[1] * inv0);   // P[i0][j 0-7]
    uint32_t pa1 = bf2(s0[2] * inv1, s0[3] * inv1);   // P[i1][j 0-7]
    uint32_t pa2 = bf2(s1[0] * inv0, s1[1] * inv0);   // P[i0][j 8-15]
    uint32_t pa3 = bf2(s1[2] * inv1, s1[3] * inv1);   // P[i1][j 8-15]

    // ---- O = P V : one k16 MMA per 8-col tile of hd=64 ----
    bf16* ob = g_ow + (size_t)(win * 16) * CDIM + head * 64;
    #pragma unroll
    for (int nt = 0; nt < 8; nt++) {
        float o[4] = {0, 0, 0, 0};
        int colb = nt * 8 + rhi;
        uint32_t b0 = packh(vb[(size_t)(2 * rlo) * 1536 + colb],
                            vb[(size_t)(2 * rlo + 1) * 1536 + colb]);
        uint32_t b1 = packh(vb[(size_t)(8 + 2 * rlo) * 1536 + colb],
                            vb[(size_t)(9 + 2 * rlo) * 1536 + colb]);
        hmma_bf16(o, pa0, pa1, pa2, pa3, b0, b1);
        int col = nt * 8 + 2 * rlo;
        *(uint32_t*)(ob + (size_t)i0 * CDIM + col) = bf2(o[0], o[1]);
        *(uint32_t*)(ob + (size_t)i1 * CDIM + col) = bf2(o[2], o[3]);
    }
}

// ---------------------------------------------------------------------------
// Launch
// ---------------------------------------------------------------------------
extern "C" void kernel_launch(void* const* d_in, const int* in_sizes, int n_in,
                              void* d_out, int out_size)
{
    const float* x      = (const float*)d_in[0];
    const float* g1     = (const float*)d_in[1];
    const float* beta1  = (const float*)d_in[2];
    const float* w_qkv  = (const float*)d_in[3];
    const float* b_qkv  = (const float*)d_in[4];
    const float* rpb    = (const float*)d_in[5];
    const float* w_proj = (const float*)d_in[6];
    const float* b_proj = (const float*)d_in[7];
    const float* g2     = (const float*)d_in[8];
    const float* beta2  = (const float*)d_in[9];
    const float* w1     = (const float*)d_in[10];
    const float* b1     = (const float*)d_in[11];
    const float* w2     = (const float*)d_in[12];
    const float* b2     = (const float*)d_in[13];
    float* out = (float*)d_out;

    bf16 *xw, *qkv, *ow, *h2, *m1, *wq, *wp, *wa, *wb;
    float *x2;
    cudaGetSymbolAddress((void**)&xw,  g_xw);
    cudaGetSymbolAddress((void**)&qkv, g_qkv);
    cudaGetSymbolAddress((void**)&ow,  g_ow);
    cudaGetSymbolAddress((void**)&x2,  g_x2);
    cudaGetSymbolAddress((void**)&h2,  g_h2);
    cudaGetSymbolAddress((void**)&m1,  g_m1);
    cudaGetSymbolAddress((void**)&wq,  g_wqkv);
    cudaGetSymbolAddress((void**)&wp,  g_wproj);
    cudaGetSymbolAddress((void**)&wa,  g_w1);
    cudaGetSymbolAddress((void**)&wb,  g_w2);

    cudaFuncSetAttribute(mma_gemm<0>, cudaFuncAttributeMaxDynamicSharedMemorySize, DYN_BYTES);
    cudaFuncSetAttribute(mma_gemm<1>, cudaFuncAttributeMaxDynamicSharedMemorySize, DYN_BYTES);
    cudaFuncSetAttribute(mma_gemm<2>, cudaFuncAttributeMaxDynamicSharedMemorySize, DYN_BYTES);
    cudaFuncSetAttribute(mma_gemm<3>, cudaFuncAttributeMaxDynamicSharedMemorySize, DYN_BYTES);

    // 0. weights -> bf16
    round_w_kernel<<<148, 256>>>(w_qkv, w_proj, w1, w2);

    // 1. LN1 + shift + window partition -> g_xw (bf16)
    ln_kernel<true><<<ROWS, 128>>>(x, g1, beta1, xw);

    // 2. QKV: [32768,1536] = xw @ wqkv^T  (bf16 out)
    mma_gemm<0><<<dim3(1536/BN, ROWS/BM), 128, DYN_BYTES>>>(xw, wq, b_qkv, nullptr, qkv, 1536, 512);

    // 3. attention -> g_ow (bf16)
    attn_mma<<<NWINDOWS, 256>>>(rpb);

    // 4. proj + window reverse + unshift + residual(x) -> g_x2 (fp32)
    mma_gemm<3><<<dim3(512/BN, ROWS/BM), 128, DYN_BYTES>>>(ow, wp, b_proj, x, x2, 512, 512);

    // 5. LN2 -> g_h2 (bf16)
    ln_kernel<false><<<ROWS, 128>>>(x2, g2, beta2, h2);

    // 6. FC1 + GELU -> g_m1 (bf16)
    mma_gemm<1><<<dim3(1024/BN, ROWS/BM), 128, DYN_BYTES>>>(h2, wa, b1, nullptr, m1, 1024, 512);

    // 7. FC2 + residual(g_x2) -> out (fp32)
    mma_gemm<2><<<dim3(512/BN, ROWS/BM), 128, DYN_BYTES>>>(m1, wb, b2, x2, out, 512, 1024);
}